// round 8
// baseline (speedup 1.0000x reference)
#include <cuda_runtime.h>

// ---------------------------------------------------------------------------
// DASAttentionGate: dwconv3x3 -> pwconv1x1 -> InstanceNorm -> offset conv3x3
//                   -> deformable conv3x3 -> LayerNorm(C) -> sigmoid -> gate
// B=4, C=O=128, H=W=96. All fp32.
// ---------------------------------------------------------------------------

#define Bc   4
#define Cc   128
#define Hc   96
#define Wc   96
#define HW   9216            // Hc*Wc
#define PIX  36864           // Bc*HW
#define KTAP 9
#define KKc  1152            // Cc*KTAP

// -------------------- device scratch (no allocations allowed) --------------
__device__ float g_h1[PIX * Cc];          // dw conv out, NCHW
__device__ float g_h2[PIX * Cc];          // pw conv out, NHWC [pix][c]
__device__ float g_dsc[PIX * Cc];         // instance-normed, NHWC [pix][c]
__device__ float g_stats[1024];           // sum[512], sumsq[512]  (b*128+c)
__device__ float g_mr[1024];              // mean[512], rstd[512]
__device__ float g_off[PIX * 18];         // offsets, [pix][18]
__device__ float g_offwT[9 * 18 * 128];   // offset weights [k][j][c]
__device__ float g_pwT[128 * 128];        // pw weights [c][o]
__device__ float g_wT[KKc * 128];         // deform weights [k*128+c][o]
__device__ float g_samp[PIX * KKc];       // gathered samples [pix][k*128+c]
__device__ float g_dc[PIX * Cc];          // deform conv out, [pix][o]

// -------------------- prep: weight transposes + zero stats -----------------
__global__ void prep_kernel(const float* __restrict__ dc_w,
                            const float* __restrict__ pw_w,
                            const float* __restrict__ off_w) {
    int i = blockIdx.x * blockDim.x + threadIdx.x;
    if (i < KKc * 128) {
        int kk = i >> 7, o = i & 127;
        int k = kk >> 7, c = kk & 127;
        g_wT[i] = dc_w[(o * 128 + c) * 9 + k];
    }
    if (i < 128 * 128) {
        int c = i >> 7, o = i & 127;
        g_pwT[i] = pw_w[o * 128 + c];
    }
    if (i < 9 * 18 * 128) {
        int k = i / 2304;
        int r = i - k * 2304;
        int j = r >> 7, c = r & 127;
        g_offwT[i] = off_w[(j * 128 + c) * 9 + k];
    }
    if (i < 1024) g_stats[i] = 0.f;
}

// -------------------- depthwise 3x3 conv (NCHW -> NCHW) --------------------
__global__ void dw_kernel(const float* __restrict__ x,
                          const float* __restrict__ dw_w,
                          const float* __restrict__ dw_b) {
    int i = blockIdx.x * blockDim.x + threadIdx.x;
    if (i >= PIX * Cc) return;
    int xw = i % Wc;
    int y  = (i / Wc) % Hc;
    int c  = (i / HW) % Cc;
    int b  = i / (HW * Cc);
    const float* xin = x + (size_t)(b * Cc + c) * HW;
    float acc = dw_b[c];
#pragma unroll
    for (int ky = 0; ky < 3; ky++) {
        int yy = y + ky - 1;
        if ((unsigned)yy >= Hc) continue;
#pragma unroll
        for (int kx = 0; kx < 3; kx++) {
            int xx = xw + kx - 1;
            if ((unsigned)xx >= Wc) continue;
            acc += dw_w[c * 9 + ky * 3 + kx] * xin[yy * Wc + xx];
        }
    }
    g_h1[i] = acc;
}

// -------------------- pointwise 1x1 conv: NCHW -> NHWC ---------------------
// Block = 32 pixels x 128 out-channels, 256 threads, 4x4 microtile.
__global__ void pw_kernel(const float* __restrict__ pw_b) {
    __shared__ float sS[Cc * 32];     // [c][px]
    int t  = threadIdx.x;
    int p0 = blockIdx.x * 32;
    int b  = p0 / HW;
    int s0 = p0 - b * HW;
    const float* src = g_h1 + (size_t)b * Cc * HW + s0;
    for (int i = t; i < Cc * 32; i += 256) {
        int c = i >> 5, px = i & 31;
        sS[i] = src[c * HW + px];
    }
    __syncthreads();
    int px0 = (t & 7) * 4;
    int o0  = (t >> 3) * 4;
    float acc[4][4];
#pragma unroll
    for (int p = 0; p < 4; p++)
#pragma unroll
        for (int q = 0; q < 4; q++) acc[p][q] = 0.f;
#pragma unroll 4
    for (int c = 0; c < 128; c++) {
        float4 sv = *(const float4*)&sS[c * 32 + px0];
        float4 wv = __ldg((const float4*)&g_pwT[c * 128 + o0]);
        float sm[4] = {sv.x, sv.y, sv.z, sv.w};
        float wm[4] = {wv.x, wv.y, wv.z, wv.w};
#pragma unroll
        for (int p = 0; p < 4; p++)
#pragma unroll
            for (int q = 0; q < 4; q++) acc[p][q] += sm[p] * wm[q];
    }
    float bb[4];
#pragma unroll
    for (int q = 0; q < 4; q++) bb[q] = pw_b[o0 + q];
#pragma unroll
    for (int p = 0; p < 4; p++) {
        float4 o;
        o.x = acc[p][0] + bb[0];
        o.y = acc[p][1] + bb[1];
        o.z = acc[p][2] + bb[2];
        o.w = acc[p][3] + bb[3];
        *(float4*)&g_h2[(size_t)(p0 + px0 + p) * 128 + o0] = o;
    }
}

// -------------------- instance-norm stats ----------------------------------
__global__ void stats_kernel() {
    int t = threadIdx.x;
    int r = blockIdx.x;                 // (b, y)
    int b = r / Hc, y = r % Hc;
    const float* p = g_h2 + (size_t)(b * HW + y * Wc) * 128 + t;
    float s = 0.f, s2 = 0.f;
    for (int x = 0; x < Wc; x++) {
        float v = p[x * 128];
        s += v; s2 += v * v;
    }
    atomicAdd(&g_stats[b * 128 + t], s);
    atomicAdd(&g_stats[512 + b * 128 + t], s2);
}

__global__ void mr_kernel() {
    int i = blockIdx.x * blockDim.x + threadIdx.x;
    if (i >= 512) return;
    float m = g_stats[i] * (1.f / HW);
    float v = g_stats[512 + i] * (1.f / HW) - m * m;
    g_mr[i] = m;
    g_mr[512 + i] = rsqrtf(v + 1e-5f);
}

__global__ void norm_kernel() {
    int i = blockIdx.x * blockDim.x + threadIdx.x;
    if (i >= PIX * Cc) return;
    int c  = i & 127;
    int pg = i >> 7;
    int b  = pg / HW;
    int bc = b * 128 + c;
    g_dsc[i] = (g_h2[i] - g_mr[bc]) * g_mr[512 + bc];
}

// -------------------- offset conv 3x3 (Cout = 18) --------------------------
// 256 threads = 8 warps; each warp handles 4 pixels, lanes partition channels.
__global__ __launch_bounds__(256) void off_kernel(const float* __restrict__ off_b) {
    extern __shared__ float w_s[];        // [k][j][c] = 20736 floats
    for (int i = threadIdx.x; i < 9 * 18 * 128; i += 256) w_s[i] = g_offwT[i];
    __syncthreads();

    int warp = threadIdx.x >> 5, lane = threadIdx.x & 31;
    int pg0  = blockIdx.x * 32 + warp * 4;
    int b    = pg0 / HW;
    const float* img = g_dsc + (size_t)b * HW * 128;
    int yb[4], xb[4];
#pragma unroll
    for (int p = 0; p < 4; p++) {
        int s = pg0 + p - b * HW;
        yb[p] = s / Wc; xb[p] = s % Wc;
    }
    int c0 = lane * 4;
    float acc[4][18];
#pragma unroll
    for (int p = 0; p < 4; p++)
#pragma unroll
        for (int j = 0; j < 18; j++) acc[p][j] = 0.f;

#pragma unroll
    for (int k = 0; k < 9; k++) {
        int dy = k / 3 - 1, dx = k % 3 - 1;
        float4 v[4];
#pragma unroll
        for (int p = 0; p < 4; p++) {
            int yy = yb[p] + dy, xx = xb[p] + dx;
            if ((unsigned)yy < Hc && (unsigned)xx < Wc)
                v[p] = *(const float4*)&img[(size_t)(yy * Wc + xx) * 128 + c0];
            else
                v[p] = make_float4(0.f, 0.f, 0.f, 0.f);
        }
        const float* wb = w_s + k * 2304;
#pragma unroll
        for (int j = 0; j < 18; j++) {
            float4 wv = *(const float4*)&wb[j * 128 + c0];
#pragma unroll
            for (int p = 0; p < 4; p++)
                acc[p][j] += wv.x * v[p].x + wv.y * v[p].y + wv.z * v[p].z + wv.w * v[p].w;
        }
    }
#pragma unroll
    for (int p = 0; p < 4; p++) {
        float keep = 0.f;
#pragma unroll
        for (int j = 0; j < 18; j++) {
            float r = acc[p][j];
            r += __shfl_xor_sync(0xffffffffu, r, 16);
            r += __shfl_xor_sync(0xffffffffu, r, 8);
            r += __shfl_xor_sync(0xffffffffu, r, 4);
            r += __shfl_xor_sync(0xffffffffu, r, 2);
            r += __shfl_xor_sync(0xffffffffu, r, 1);
            if (lane == j) keep = r;
        }
        if (lane < 18) g_off[(size_t)(pg0 + p) * 18 + lane] = keep + off_b[lane];
    }
}

// -------------------- bilinear gather (im2col for deform conv) -------------
__device__ __forceinline__ void sample_corner(const float* img, int c0,
                                              float yf, float xf, float w,
                                              float4& acc) {
    if (yf >= 0.f && yf <= (float)(Hc - 1) && xf >= 0.f && xf <= (float)(Wc - 1)) {
        int yi = (int)yf, xi = (int)xf;
        float4 v = *(const float4*)&img[(size_t)(yi * Wc + xi) * 128 + c0];
        acc.x += w * v.x; acc.y += w * v.y; acc.z += w * v.z; acc.w += w * v.w;
    }
}

__global__ __launch_bounds__(256) void gather_kernel() {
    int warp = threadIdx.x >> 5, lane = threadIdx.x & 31;
    int pg = blockIdx.x * 8 + warp;
    int b  = pg / HW;
    int s  = pg - b * HW;
    int y  = s / Wc, xw = s % Wc;
    const float* img  = g_dsc + (size_t)b * HW * 128;
    const float* op   = g_off + (size_t)pg * 18;
    float*       outp = g_samp + (size_t)pg * KKc;
    int c0 = lane * 4;
#pragma unroll
    for (int k = 0; k < 9; k++) {
        float ys = (float)(y + (k / 3) - 1) + op[2 * k];
        float xs = (float)(xw + (k % 3) - 1) + op[2 * k + 1];
        float y0 = floorf(ys), x0 = floorf(xs);
        float wy = ys - y0, wx = xs - x0;
        float4 acc = make_float4(0.f, 0.f, 0.f, 0.f);
        sample_corner(img, c0, y0,       x0,       (1.f - wy) * (1.f - wx), acc);
        sample_corner(img, c0, y0,       x0 + 1.f, (1.f - wy) * wx,         acc);
        sample_corner(img, c0, y0 + 1.f, x0,       wy * (1.f - wx),         acc);
        sample_corner(img, c0, y0 + 1.f, x0 + 1.f, wy * wx,                 acc);
        *(float4*)&outp[k * 128 + c0] = acc;
    }
}

// -------------------- deform conv GEMM: [36864 x 1152] * [1152 x 128] ------
// BM=64, BN=128, BK=16, 256 threads, 4x8 microtile.
__global__ __launch_bounds__(256) void gemm_kernel(const float* __restrict__ dc_b) {
    __shared__ float As[16 * 64];    // [kk][m]
    __shared__ float Bs[16 * 128];   // [kk][o]
    int t  = threadIdx.x;
    int m0 = blockIdx.x * 64;

    int lm  = t >> 2;            // 0..63
    int lk4 = (t & 3) * 4;       // 0,4,8,12
    int bk  = t >> 4;            // 0..15
    int bo  = (t & 15) * 8;      // 0..120

    int tm0 = (t & 15) * 4;      // 0..60
    int to0 = (t >> 4) * 8;      // 0..120

    float acc[4][8];
#pragma unroll
    for (int i = 0; i < 4; i++)
#pragma unroll
        for (int j = 0; j < 8; j++) acc[i][j] = 0.f;

    for (int k0 = 0; k0 < KKc; k0 += 16) {
        float4 a  = *(const float4*)&g_samp[(size_t)(m0 + lm) * KKc + k0 + lk4];
        float4 b0 = *(const float4*)&g_wT[(size_t)(k0 + bk) * 128 + bo];
        float4 b1 = *(const float4*)&g_wT[(size_t)(k0 + bk) * 128 + bo + 4];
        As[(lk4 + 0) * 64 + lm] = a.x;
        As[(lk4 + 1) * 64 + lm] = a.y;
        As[(lk4 + 2) * 64 + lm] = a.z;
        As[(lk4 + 3) * 64 + lm] = a.w;
        *(float4*)&Bs[bk * 128 + bo]     = b0;
        *(float4*)&Bs[bk * 128 + bo + 4] = b1;
        __syncthreads();
#pragma unroll
        for (int kk = 0; kk < 16; kk++) {
            float4 av  = *(const float4*)&As[kk * 64 + tm0];
            float4 bv0 = *(const float4*)&Bs[kk * 128 + to0];
            float4 bv1 = *(const float4*)&Bs[kk * 128 + to0 + 4];
            float am[4] = {av.x, av.y, av.z, av.w};
            float bn[8] = {bv0.x, bv0.y, bv0.z, bv0.w, bv1.x, bv1.y, bv1.z, bv1.w};
#pragma unroll
            for (int i = 0; i < 4; i++)
#pragma unroll
                for (int j = 0; j < 8; j++) acc[i][j] += am[i] * bn[j];
        }
        __syncthreads();
    }
    float bb[8];
#pragma unroll
    for (int j = 0; j < 8; j++) bb[j] = dc_b[to0 + j];
#pragma unroll
    for (int i = 0; i < 4; i++) {
        int m = m0 + tm0 + i;
        float4 o0v, o1v;
        o0v.x = acc[i][0] + bb[0]; o0v.y = acc[i][1] + bb[1];
        o0v.z = acc[i][2] + bb[2]; o0v.w = acc[i][3] + bb[3];
        o1v.x = acc[i][4] + bb[4]; o1v.y = acc[i][5] + bb[5];
        o1v.z = acc[i][6] + bb[6]; o1v.w = acc[i][7] + bb[7];
        *(float4*)&g_dc[(size_t)m * 128 + to0]     = o0v;
        *(float4*)&g_dc[(size_t)m * 128 + to0 + 4] = o1v;
    }
}

// -------------------- LayerNorm(C) + sigmoid gate, NHWC -> NCHW ------------
__global__ __launch_bounds__(128) void final_kernel(const float* __restrict__ ln_g,
                                                    const float* __restrict__ ln_b,
                                                    float* __restrict__ out) {
    __shared__ float sout[128 * 33];
    __shared__ float red[8];
    int t = threadIdx.x;
    int lane = t & 31, wid = t >> 5;
    int bid = blockIdx.x;
    int b = bid / 288;
    int r = bid - b * 288;
    int y = r / 3;
    int x0 = (r % 3) * 32;
    int pgbase = b * HW + y * Wc + x0;
    float gv = ln_g[t], bvv = ln_b[t];

    for (int px = 0; px < 32; px++) {
        int pg = pgbase + px;
        float v = g_dc[(size_t)pg * 128 + t];
        float s = v, s2 = v * v;
#pragma unroll
        for (int o = 16; o; o >>= 1) {
            s  += __shfl_xor_sync(0xffffffffu, s,  o);
            s2 += __shfl_xor_sync(0xffffffffu, s2, o);
        }
        if (lane == 0) { red[wid] = s; red[4 + wid] = s2; }
        __syncthreads();
        float sum = red[0] + red[1] + red[2] + red[3];
        float sq  = red[4] + red[5] + red[6] + red[7];
        float mean = sum * (1.f / 128.f);
        float var  = sq * (1.f / 128.f) - mean * mean;
        float rstd = rsqrtf(var + 1e-5f);
        float ln   = (v - mean) * rstd * gv + bvv;
        float attn = 1.f / (1.f + expf(-ln));
        sout[t * 33 + px] = g_dsc[(size_t)pg * 128 + t] * attn;
        __syncthreads();
    }
    // transpose write NHWC -> NCHW, coalesced
    for (int j = 0; j < 32; j++) {
        int flat = j * 128 + t;
        int c = flat >> 5, px = flat & 31;
        out[(size_t)(b * 128 + c) * HW + y * Wc + x0 + px] = sout[c * 33 + px];
    }
}

// ---------------------------------------------------------------------------
extern "C" void kernel_launch(void* const* d_in, const int* in_sizes, int n_in,
                              void* d_out, int out_size) {
    const float* x    = (const float*)d_in[0];
    const float* dw_w = (const float*)d_in[1];
    const float* dw_b = (const float*)d_in[2];
    const float* pw_w = (const float*)d_in[3];
    const float* pw_b = (const float*)d_in[4];
    const float* off_w = (const float*)d_in[5];
    const float* off_b = (const float*)d_in[6];
    const float* dc_w = (const float*)d_in[7];
    const float* dc_b = (const float*)d_in[8];
    const float* ln_g = (const float*)d_in[9];
    const float* ln_b = (const float*)d_in[10];
    float* out = (float*)d_out;

    cudaFuncSetAttribute(off_kernel, cudaFuncAttributeMaxDynamicSharedMemorySize,
                         9 * 18 * 128 * 4);

    prep_kernel<<<576, 256>>>(dc_w, pw_w, off_w);
    dw_kernel<<<18432, 256>>>(x, dw_w, dw_b);
    pw_kernel<<<1152, 256>>>(pw_b);
    stats_kernel<<<384, 128>>>();
    mr_kernel<<<2, 256>>>();
    norm_kernel<<<18432, 256>>>();
    off_kernel<<<1152, 256, 9 * 18 * 128 * 4>>>(off_b);
    gather_kernel<<<4608, 256>>>();
    gemm_kernel<<<576, 256>>>(dc_b);
    final_kernel<<<1152, 128>>>(ln_g, ln_b, out);
}

// round 9
// speedup vs baseline: 1.7474x; 1.7474x over previous
#include <cuda_runtime.h>

// ---------------------------------------------------------------------------
// DASAttentionGate. B=4, C=O=128, H=W=96, fp32.
// dw3x3 -> pw1x1 -> InstNorm -> offconv3x3 -> [fused gather+GEMM(f32x2)+LN+gate]
// ---------------------------------------------------------------------------

#define Cc   128
#define Hc   96
#define Wc   96
#define HW   9216
#define PIX  36864
#define KKc  1152

__device__ float g_h1[PIX * Cc];          // dw out, NCHW
__device__ float g_h2[PIX * Cc];          // pw out, NHWC
__device__ float g_dsc[PIX * Cc];         // instance-normed, NHWC
__device__ float g_stats[1024];
__device__ float g_mr[1024];
__device__ float g_off[PIX * 18];
__device__ float g_offwT[9 * 18 * 128];
__device__ float g_pwT[128 * 128];
__device__ float g_wT[KKc * 128];         // deform weights [k*128+c][o]

// packed f32x2 helpers
#define FMA2(d, a, b, c) \
    asm("fma.rn.f32x2 %0, %1, %2, %3;" : "=l"(d) : "l"(a), "l"(b), "l"(c))
#define PACK2(d, x) \
    asm("mov.b64 %0, {%1, %1};" : "=l"(d) : "f"(x))
#define UNPACK2(lo, hi, s) \
    asm("mov.b64 {%0, %1}, %2;" : "=f"(lo), "=f"(hi) : "l"(s))

// -------------------- prep ---------------------------------------------------
__global__ void prep_kernel(const float* __restrict__ dc_w,
                            const float* __restrict__ pw_w,
                            const float* __restrict__ off_w) {
    int i = blockIdx.x * blockDim.x + threadIdx.x;
    if (i < KKc * 128) {
        int kk = i >> 7, o = i & 127;
        int k = kk >> 7, c = kk & 127;
        g_wT[i] = dc_w[(o * 128 + c) * 9 + k];
    }
    if (i < 128 * 128) {
        int c = i >> 7, o = i & 127;
        g_pwT[i] = pw_w[o * 128 + c];
    }
    if (i < 9 * 18 * 128) {
        int k = i / 2304;
        int r = i - k * 2304;
        int j = r >> 7, c = r & 127;
        g_offwT[i] = off_w[(j * 128 + c) * 9 + k];
    }
    if (i < 1024) g_stats[i] = 0.f;
}

// -------------------- depthwise 3x3 -----------------------------------------
__global__ void dw_kernel(const float* __restrict__ x,
                          const float* __restrict__ dw_w,
                          const float* __restrict__ dw_b) {
    int i = blockIdx.x * blockDim.x + threadIdx.x;
    if (i >= PIX * Cc) return;
    int xw = i % Wc;
    int y  = (i / Wc) % Hc;
    int c  = (i / HW) % Cc;
    int b  = i / (HW * Cc);
    const float* xin = x + (size_t)(b * Cc + c) * HW;
    float acc = dw_b[c];
#pragma unroll
    for (int ky = 0; ky < 3; ky++) {
        int yy = y + ky - 1;
        if ((unsigned)yy >= Hc) continue;
#pragma unroll
        for (int kx = 0; kx < 3; kx++) {
            int xx = xw + kx - 1;
            if ((unsigned)xx >= Wc) continue;
            acc += dw_w[c * 9 + ky * 3 + kx] * xin[yy * Wc + xx];
        }
    }
    g_h1[i] = acc;
}

// -------------------- pointwise 1x1: NCHW -> NHWC ---------------------------
__global__ void pw_kernel(const float* __restrict__ pw_b) {
    __shared__ float sS[Cc * 32];
    int t  = threadIdx.x;
    int p0 = blockIdx.x * 32;
    int b  = p0 / HW;
    int s0 = p0 - b * HW;
    const float* src = g_h1 + (size_t)b * Cc * HW + s0;
    for (int i = t; i < Cc * 32; i += 256) {
        int c = i >> 5, px = i & 31;
        sS[i] = src[c * HW + px];
    }
    __syncthreads();
    int px0 = (t & 7) * 4;
    int o0  = (t >> 3) * 4;
    float acc[4][4];
#pragma unroll
    for (int p = 0; p < 4; p++)
#pragma unroll
        for (int q = 0; q < 4; q++) acc[p][q] = 0.f;
#pragma unroll 4
    for (int c = 0; c < 128; c++) {
        float4 sv = *(const float4*)&sS[c * 32 + px0];
        float4 wv = __ldg((const float4*)&g_pwT[c * 128 + o0]);
        float sm[4] = {sv.x, sv.y, sv.z, sv.w};
        float wm[4] = {wv.x, wv.y, wv.z, wv.w};
#pragma unroll
        for (int p = 0; p < 4; p++)
#pragma unroll
            for (int q = 0; q < 4; q++) acc[p][q] += sm[p] * wm[q];
    }
#pragma unroll
    for (int p = 0; p < 4; p++) {
        float4 o;
        o.x = acc[p][0] + pw_b[o0];
        o.y = acc[p][1] + pw_b[o0 + 1];
        o.z = acc[p][2] + pw_b[o0 + 2];
        o.w = acc[p][3] + pw_b[o0 + 3];
        *(float4*)&g_h2[(size_t)(p0 + px0 + p) * 128 + o0] = o;
    }
}

// -------------------- instance norm -----------------------------------------
__global__ void stats_kernel() {
    int t = threadIdx.x;
    int r = blockIdx.x;
    int b = r / Hc, y = r % Hc;
    const float* p = g_h2 + (size_t)(b * HW + y * Wc) * 128 + t;
    float s = 0.f, s2 = 0.f;
    for (int x = 0; x < Wc; x++) {
        float v = p[x * 128];
        s += v; s2 += v * v;
    }
    atomicAdd(&g_stats[b * 128 + t], s);
    atomicAdd(&g_stats[512 + b * 128 + t], s2);
}

__global__ void mr_kernel() {
    int i = blockIdx.x * blockDim.x + threadIdx.x;
    if (i >= 512) return;
    float m = g_stats[i] * (1.f / HW);
    float v = g_stats[512 + i] * (1.f / HW) - m * m;
    g_mr[i] = m;
    g_mr[512 + i] = rsqrtf(v + 1e-5f);
}

__global__ void norm_kernel() {
    int i = blockIdx.x * blockDim.x + threadIdx.x;
    if (i >= PIX * Cc) return;
    int c  = i & 127;
    int pg = i >> 7;
    int b  = pg / HW;
    int bc = b * 128 + c;
    g_dsc[i] = (g_h2[i] - g_mr[bc]) * g_mr[512 + bc];
}

// -------------------- offset conv 3x3 (Cout=18) ------------------------------
__global__ __launch_bounds__(256) void off_kernel(const float* __restrict__ off_b) {
    extern __shared__ float w_s[];
    for (int i = threadIdx.x; i < 9 * 18 * 128; i += 256) w_s[i] = g_offwT[i];
    __syncthreads();

    int warp = threadIdx.x >> 5, lane = threadIdx.x & 31;
    int pg0  = blockIdx.x * 32 + warp * 4;
    int b    = pg0 / HW;
    const float* img = g_dsc + (size_t)b * HW * 128;
    int yb[4], xb[4];
#pragma unroll
    for (int p = 0; p < 4; p++) {
        int s = pg0 + p - b * HW;
        yb[p] = s / Wc; xb[p] = s % Wc;
    }
    int c0 = lane * 4;
    float acc[4][18];
#pragma unroll
    for (int p = 0; p < 4; p++)
#pragma unroll
        for (int j = 0; j < 18; j++) acc[p][j] = 0.f;

#pragma unroll
    for (int k = 0; k < 9; k++) {
        int dy = k / 3 - 1, dx = k % 3 - 1;
        float4 v[4];
#pragma unroll
        for (int p = 0; p < 4; p++) {
            int yy = yb[p] + dy, xx = xb[p] + dx;
            if ((unsigned)yy < Hc && (unsigned)xx < Wc)
                v[p] = *(const float4*)&img[(size_t)(yy * Wc + xx) * 128 + c0];
            else
                v[p] = make_float4(0.f, 0.f, 0.f, 0.f);
        }
        const float* wb = w_s + k * 2304;
#pragma unroll
        for (int j = 0; j < 18; j++) {
            float4 wv = *(const float4*)&wb[j * 128 + c0];
#pragma unroll
            for (int p = 0; p < 4; p++)
                acc[p][j] += wv.x * v[p].x + wv.y * v[p].y + wv.z * v[p].z + wv.w * v[p].w;
        }
    }
#pragma unroll
    for (int p = 0; p < 4; p++) {
        float keep = 0.f;
#pragma unroll
        for (int j = 0; j < 18; j++) {
            float r = acc[p][j];
            r += __shfl_xor_sync(0xffffffffu, r, 16);
            r += __shfl_xor_sync(0xffffffffu, r, 8);
            r += __shfl_xor_sync(0xffffffffu, r, 4);
            r += __shfl_xor_sync(0xffffffffu, r, 2);
            r += __shfl_xor_sync(0xffffffffu, r, 1);
            if (lane == j) keep = r;
        }
        if (lane < 18) g_off[(size_t)(pg0 + p) * 18 + lane] = keep + off_b[lane];
    }
}

// ---------------------------------------------------------------------------
// Fused: per-tap bilinear gather -> GEMM (f32x2) -> bias -> LayerNorm(C)
//        -> sigmoid gate -> NCHW output.  Block: 64 px x 128 out, 256 thr.
// smem: As[128 kk][64 m] swizzled (32KB) + Bs[128 kk][128 o] (64KB) = 96KB.
// Epilogue reuses smem as sdc[64 px][132].
// ---------------------------------------------------------------------------
#define FUSED_SMEM 98304

#define QFMA(I, AV)                           \
    {                                         \
        unsigned long long a2_;               \
        PACK2(a2_, AV);                       \
        FMA2(acc[I][0], a2_, b0, acc[I][0]);  \
        FMA2(acc[I][1], a2_, b1, acc[I][1]);  \
        FMA2(acc[I][2], a2_, b2, acc[I][2]);  \
        FMA2(acc[I][3], a2_, b3, acc[I][3]);  \
    }

__global__ __launch_bounds__(256, 2) void fused_kernel(
        const float* __restrict__ dc_b,
        const float* __restrict__ ln_g,
        const float* __restrict__ ln_b,
        float* __restrict__ out) {
    extern __shared__ float smf[];
    float* As = smf;              // [kk][m^swz], 8192 floats
    float* Bs = smf + 8192;       // [kk][o], 16384 floats

    int t = threadIdx.x;
    int w = t >> 5, l = t & 31;
    int m0 = blockIdx.x * 64;
    int b  = m0 / HW;
    int s0 = m0 - b * HW;
    const float* img = g_dsc + (size_t)b * HW * 128;

    // microtile: warps 2(m) x 4(n); lanes 8(m) x 4(n); thread = 4m x 8n
    int m0t = (w & 1) * 32 + (l >> 2) * 4;
    int n0t = (w >> 1) * 32 + (l & 3) * 8;

    unsigned long long acc[4][4];
#pragma unroll
    for (int i = 0; i < 4; i++)
#pragma unroll
        for (int j = 0; j < 4; j++) acc[i][j] = 0ull;

    int c0 = 4 * l;
    int swzg = (l & 7) << 2;

    for (int k = 0; k < 9; k++) {
        __syncthreads();   // previous tap fully consumed

        // ---- gather tap k into As (warp: 8 px, lane: 4 channels) ----
        {
            int dy = k / 3 - 1, dx = k % 3 - 1;
#pragma unroll 1
            for (int ii = 0; ii < 8; ii++) {
                int px = w * 8 + ii;
                int s  = s0 + px;
                int y  = s / Wc, xw = s - y * Wc;
                float2 o = *(const float2*)&g_off[(size_t)(m0 + px) * 18 + 2 * k];
                float ys = (float)(y + dy) + o.x;
                float xs = (float)(xw + dx) + o.y;
                float y0f = floorf(ys), x0f = floorf(xs);
                float wy = ys - y0f, wx = xs - x0f;
                int y0i = (int)y0f, x0i = (int)x0f;
                int y1i = y0i + 1, x1i = x0i + 1;
                float w00 = (1.f - wy) * (1.f - wx);
                float w01 = (1.f - wy) * wx;
                float w10 = wy * (1.f - wx);
                float w11 = wy * wx;
                bool vy0 = (unsigned)y0i < (unsigned)Hc;
                bool vy1 = (unsigned)y1i < (unsigned)Hc;
                bool vx0 = (unsigned)x0i < (unsigned)Wc;
                bool vx1 = (unsigned)x1i < (unsigned)Wc;
                if (!(vy0 && vx0)) w00 = 0.f;
                if (!(vy0 && vx1)) w01 = 0.f;
                if (!(vy1 && vx0)) w10 = 0.f;
                if (!(vy1 && vx1)) w11 = 0.f;
                int yc0 = min(Hc - 1, max(0, y0i));
                int yc1 = min(Hc - 1, max(0, y1i));
                int xc0 = min(Wc - 1, max(0, x0i));
                int xc1 = min(Wc - 1, max(0, x1i));
                float4 v00 = *(const float4*)&img[(size_t)(yc0 * Wc + xc0) * 128 + c0];
                float4 v01 = *(const float4*)&img[(size_t)(yc0 * Wc + xc1) * 128 + c0];
                float4 v10 = *(const float4*)&img[(size_t)(yc1 * Wc + xc0) * 128 + c0];
                float4 v11 = *(const float4*)&img[(size_t)(yc1 * Wc + xc1) * 128 + c0];
                int base = c0 * 64 + (px ^ swzg);
                As[base]       = w00 * v00.x + w01 * v01.x + w10 * v10.x + w11 * v11.x;
                As[base + 64]  = w00 * v00.y + w01 * v01.y + w10 * v10.y + w11 * v11.y;
                As[base + 128] = w00 * v00.z + w01 * v01.z + w10 * v10.z + w11 * v11.z;
                As[base + 192] = w00 * v00.w + w01 * v01.w + w10 * v10.w + w11 * v11.w;
            }
        }

        // ---- copy B tap k into Bs (plain 64KB copy, layout identical) ----
        {
            const float4* wsrc = (const float4*)(g_wT + (size_t)k * 16384);
            float4* bdst = (float4*)Bs;
#pragma unroll
            for (int j = 0; j < 16; j++) bdst[t + j * 256] = wsrc[t + j * 256];
        }
        __syncthreads();

        // ---- GEMM over this tap's 128 k-slices ----
#pragma unroll 8
        for (int kk = 0; kk < 128; kk++) {
            int swz = ((kk >> 2) & 7) << 2;
            float4 a0 = *(const float4*)&As[kk * 64 + (m0t ^ swz)];
            const unsigned long long* bp =
                (const unsigned long long*)&Bs[kk * 128 + n0t];
            unsigned long long b0 = bp[0], b1 = bp[1], b2 = bp[2], b3 = bp[3];
            QFMA(0, a0.x); QFMA(1, a0.y); QFMA(2, a0.z); QFMA(3, a0.w);
        }
    }

    // ---- epilogue: bias + stage into sdc[px][132] ----
    __syncthreads();
    float* sdc = smf;
    {
#pragma unroll
        for (int i = 0; i < 4; i++) {
            float* row = &sdc[(m0t + i) * 132 + n0t];
#pragma unroll
            for (int jj = 0; jj < 4; jj++) {
                float lo, hi;
                UNPACK2(lo, hi, acc[i][jj]);
                row[2 * jj]     = lo + dc_b[n0t + 2 * jj];
                row[2 * jj + 1] = hi + dc_b[n0t + 2 * jj + 1];
            }
        }
    }
    __syncthreads();

    // ---- LayerNorm(C) + sigmoid gate: warp-per-pixel, lane = 4 channels ----
    {
        float4 gv = *(const float4*)&ln_g[c0];
        float4 bv = *(const float4*)&ln_b[c0];
#pragma unroll 1
        for (int ii = 0; ii < 8; ii++) {
            int px = w * 8 + ii;
            int pg = m0 + px;
            float4 d = *(const float4*)&sdc[px * 132 + c0];
            float s  = d.x + d.y + d.z + d.w;
            float s2 = d.x * d.x + d.y * d.y + d.z * d.z + d.w * d.w;
#pragma unroll
            for (int o = 16; o; o >>= 1) {
                s  += __shfl_xor_sync(0xffffffffu, s,  o);
                s2 += __shfl_xor_sync(0xffffffffu, s2, o);
            }
            float mean = s * (1.f / 128.f);
            float var  = s2 * (1.f / 128.f) - mean * mean;
            float rstd = rsqrtf(var + 1e-5f);
            float4 ds = *(const float4*)&g_dsc[(size_t)pg * 128 + c0];
            float a;
            float4 r;
            a = (d.x - mean) * rstd * gv.x + bv.x; r.x = ds.x / (1.f + expf(-a));
            a = (d.y - mean) * rstd * gv.y + bv.y; r.y = ds.y / (1.f + expf(-a));
            a = (d.z - mean) * rstd * gv.z + bv.z; r.z = ds.z / (1.f + expf(-a));
            a = (d.w - mean) * rstd * gv.w + bv.w; r.w = ds.w / (1.f + expf(-a));
            *(float4*)&sdc[px * 132 + c0] = r;   // own rows only
        }
    }
    __syncthreads();

    // ---- transpose-out: sdc[px][c] -> NCHW, coalesced ----
    {
        float* obase = out + (size_t)b * 128 * HW + s0;
#pragma unroll 4
        for (int j = 0; j < 32; j++) {
            int flat = t + j * 256;       // 0..8191
            int c = flat >> 6, px = flat & 63;
            obase[(size_t)c * HW + px] = sdc[px * 132 + c];
        }
    }
}

// ---------------------------------------------------------------------------
extern "C" void kernel_launch(void* const* d_in, const int* in_sizes, int n_in,
                              void* d_out, int out_size) {
    const float* x     = (const float*)d_in[0];
    const float* dw_w  = (const float*)d_in[1];
    const float* dw_b  = (const float*)d_in[2];
    const float* pw_w  = (const float*)d_in[3];
    const float* pw_b  = (const float*)d_in[4];
    const float* off_w = (const float*)d_in[5];
    const float* off_b = (const float*)d_in[6];
    const float* dc_w  = (const float*)d_in[7];
    const float* dc_b  = (const float*)d_in[8];
    const float* ln_g  = (const float*)d_in[9];
    const float* ln_b  = (const float*)d_in[10];
    float* out = (float*)d_out;

    cudaFuncSetAttribute(off_kernel, cudaFuncAttributeMaxDynamicSharedMemorySize,
                         9 * 18 * 128 * 4);
    cudaFuncSetAttribute(fused_kernel, cudaFuncAttributeMaxDynamicSharedMemorySize,
                         FUSED_SMEM);

    prep_kernel<<<576, 256>>>(dc_w, pw_w, off_w);
    dw_kernel<<<18432, 256>>>(x, dw_w, dw_b);
    pw_kernel<<<1152, 256>>>(pw_b);
    stats_kernel<<<384, 128>>>();
    mr_kernel<<<2, 256>>>();
    norm_kernel<<<18432, 256>>>();
    off_kernel<<<1152, 256, 9 * 18 * 128 * 4>>>(off_b);
    fused_kernel<<<576, 256, FUSED_SMEM>>>(dc_b, ln_g, ln_b, out);
}

// round 11
// speedup vs baseline: 1.8910x; 1.0822x over previous
#include <cuda_runtime.h>
#include <cstdint>

// ---------------------------------------------------------------------------
// DASAttentionGate. B=4, C=O=128, H=W=96, fp32.
// dw3x3 -> pw1x1 -> InstNorm -> offconv3x3 ->
//   [fused: per-tap bilinear gather -> mma.sync TF32x3 -> LN -> sigmoid gate]
// ---------------------------------------------------------------------------

#define Cc   128
#define Hc   96
#define Wc   96
#define HW   9216
#define PIX  36864

__device__ float g_h1[PIX * Cc];          // dw out, NCHW
__device__ float g_h2[PIX * Cc];          // pw out, NHWC
__device__ float g_dsc[PIX * Cc];         // instance-normed, NHWC
__device__ float g_stats[1024];
__device__ float g_mr[1024];
__device__ float g_off[PIX * 18];
__device__ float g_offwT[9 * 18 * 128];
__device__ float g_pwT[128 * 128];
__device__ float g_wB[9 * 16384];         // deform weights per tap: [n*128+c]

// -------------------- TF32 helpers ------------------------------------------
__device__ __forceinline__ uint32_t tf32r(float v) {
    uint32_t r;
    asm("cvt.rna.tf32.f32 %0, %1;" : "=r"(r) : "f"(v));
    return r;
}

#define MMA_TF32(D, A, B0, B1)                                              \
    asm volatile("mma.sync.aligned.m16n8k8.row.col.f32.tf32.tf32.f32 "      \
        "{%0,%1,%2,%3}, {%4,%5,%6,%7}, {%8,%9}, {%0,%1,%2,%3};"             \
        : "+f"((D)[0]), "+f"((D)[1]), "+f"((D)[2]), "+f"((D)[3])            \
        : "r"((A)[0]), "r"((A)[1]), "r"((A)[2]), "r"((A)[3]),               \
          "r"(B0), "r"(B1))

// -------------------- prep: weight images + zero stats ----------------------
__global__ void prep_kernel(const float* __restrict__ dc_w,
                            const float* __restrict__ pw_w,
                            const float* __restrict__ off_w) {
    int i = blockIdx.x * blockDim.x + threadIdx.x;
    if (i < 9 * 16384) {
        int tap = i >> 14;
        int r   = i & 16383;
        int n   = r >> 7, c = r & 127;
        g_wB[i] = dc_w[(n * 128 + c) * 9 + tap];
    }
    if (i < 128 * 128) {
        int c = i >> 7, o = i & 127;
        g_pwT[i] = pw_w[o * 128 + c];
    }
    if (i < 9 * 18 * 128) {
        int k = i / 2304;
        int r = i - k * 2304;
        int j = r >> 7, c = r & 127;
        g_offwT[i] = off_w[(j * 128 + c) * 9 + k];
    }
    if (i < 1024) g_stats[i] = 0.f;
}

// -------------------- depthwise 3x3 -----------------------------------------
__global__ void dw_kernel(const float* __restrict__ x,
                          const float* __restrict__ dw_w,
                          const float* __restrict__ dw_b) {
    int i = blockIdx.x * blockDim.x + threadIdx.x;
    if (i >= PIX * Cc) return;
    int xw = i % Wc;
    int y  = (i / Wc) % Hc;
    int c  = (i / HW) % Cc;
    int b  = i / (HW * Cc);
    const float* xin = x + (size_t)(b * Cc + c) * HW;
    float acc = dw_b[c];
#pragma unroll
    for (int ky = 0; ky < 3; ky++) {
        int yy = y + ky - 1;
        if ((unsigned)yy >= Hc) continue;
#pragma unroll
        for (int kx = 0; kx < 3; kx++) {
            int xx = xw + kx - 1;
            if ((unsigned)xx >= Wc) continue;
            acc += dw_w[c * 9 + ky * 3 + kx] * xin[yy * Wc + xx];
        }
    }
    g_h1[i] = acc;
}

// -------------------- pointwise 1x1: NCHW -> NHWC ---------------------------
__global__ void pw_kernel(const float* __restrict__ pw_b) {
    __shared__ float sS[Cc * 32];
    int t  = threadIdx.x;
    int p0 = blockIdx.x * 32;
    int b  = p0 / HW;
    int s0 = p0 - b * HW;
    const float* src = g_h1 + (size_t)b * Cc * HW + s0;
    for (int i = t; i < Cc * 32; i += 256) {
        int c = i >> 5, px = i & 31;
        sS[i] = src[c * HW + px];
    }
    __syncthreads();
    int px0 = (t & 7) * 4;
    int o0  = (t >> 3) * 4;
    float acc[4][4];
#pragma unroll
    for (int p = 0; p < 4; p++)
#pragma unroll
        for (int q = 0; q < 4; q++) acc[p][q] = 0.f;
#pragma unroll 4
    for (int c = 0; c < 128; c++) {
        float4 sv = *(const float4*)&sS[c * 32 + px0];
        float4 wv = __ldg((const float4*)&g_pwT[c * 128 + o0]);
        float sm[4] = {sv.x, sv.y, sv.z, sv.w};
        float wm[4] = {wv.x, wv.y, wv.z, wv.w};
#pragma unroll
        for (int p = 0; p < 4; p++)
#pragma unroll
            for (int q = 0; q < 4; q++) acc[p][q] += sm[p] * wm[q];
    }
#pragma unroll
    for (int p = 0; p < 4; p++) {
        float4 o;
        o.x = acc[p][0] + pw_b[o0];
        o.y = acc[p][1] + pw_b[o0 + 1];
        o.z = acc[p][2] + pw_b[o0 + 2];
        o.w = acc[p][3] + pw_b[o0 + 3];
        *(float4*)&g_h2[(size_t)(p0 + px0 + p) * 128 + o0] = o;
    }
}

// -------------------- instance norm -----------------------------------------
__global__ void stats_kernel() {
    int t = threadIdx.x;
    int r = blockIdx.x;
    int b = r / Hc, y = r % Hc;
    const float* p = g_h2 + (size_t)(b * HW + y * Wc) * 128 + t;
    float s = 0.f, s2 = 0.f;
    for (int x = 0; x < Wc; x++) {
        float v = p[x * 128];
        s += v; s2 += v * v;
    }
    atomicAdd(&g_stats[b * 128 + t], s);
    atomicAdd(&g_stats[512 + b * 128 + t], s2);
}

__global__ void mr_kernel() {
    int i = blockIdx.x * blockDim.x + threadIdx.x;
    if (i >= 512) return;
    float m = g_stats[i] * (1.f / HW);
    float v = g_stats[512 + i] * (1.f / HW) - m * m;
    g_mr[i] = m;
    g_mr[512 + i] = rsqrtf(v + 1e-5f);
}

__global__ void norm_kernel() {
    int i = blockIdx.x * blockDim.x + threadIdx.x;
    if (i >= PIX * Cc) return;
    int c  = i & 127;
    int pg = i >> 7;
    int b  = pg / HW;
    int bc = b * 128 + c;
    g_dsc[i] = (g_h2[i] - g_mr[bc]) * g_mr[512 + bc];
}

// -------------------- offset conv 3x3 (Cout=18) ------------------------------
__global__ __launch_bounds__(256) void off_kernel(const float* __restrict__ off_b) {
    extern __shared__ float w_s[];
    for (int i = threadIdx.x; i < 9 * 18 * 128; i += 256) w_s[i] = g_offwT[i];
    __syncthreads();

    int warp = threadIdx.x >> 5, lane = threadIdx.x & 31;
    int pg0  = blockIdx.x * 32 + warp * 4;
    int b    = pg0 / HW;
    const float* img = g_dsc + (size_t)b * HW * 128;
    int yb[4], xb[4];
#pragma unroll
    for (int p = 0; p < 4; p++) {
        int s = pg0 + p - b * HW;
        yb[p] = s / Wc; xb[p] = s % Wc;
    }
    int c0 = lane * 4;
    float acc[4][18];
#pragma unroll
    for (int p = 0; p < 4; p++)
#pragma unroll
        for (int j = 0; j < 18; j++) acc[p][j] = 0.f;

#pragma unroll
    for (int k = 0; k < 9; k++) {
        int dy = k / 3 - 1, dx = k % 3 - 1;
        float4 v[4];
#pragma unroll
        for (int p = 0; p < 4; p++) {
            int yy = yb[p] + dy, xx = xb[p] + dx;
            if ((unsigned)yy < Hc && (unsigned)xx < Wc)
                v[p] = *(const float4*)&img[(size_t)(yy * Wc + xx) * 128 + c0];
            else
                v[p] = make_float4(0.f, 0.f, 0.f, 0.f);
        }
        const float* wb = w_s + k * 2304;
#pragma unroll
        for (int j = 0; j < 18; j++) {
            float4 wv = *(const float4*)&wb[j * 128 + c0];
#pragma unroll
            for (int p = 0; p < 4; p++)
                acc[p][j] += wv.x * v[p].x + wv.y * v[p].y + wv.z * v[p].z + wv.w * v[p].w;
        }
    }
#pragma unroll
    for (int p = 0; p < 4; p++) {
        float keep = 0.f;
#pragma unroll
        for (int j = 0; j < 18; j++) {
            float r = acc[p][j];
            r += __shfl_xor_sync(0xffffffffu, r, 16);
            r += __shfl_xor_sync(0xffffffffu, r, 8);
            r += __shfl_xor_sync(0xffffffffu, r, 4);
            r += __shfl_xor_sync(0xffffffffu, r, 2);
            r += __shfl_xor_sync(0xffffffffu, r, 1);
            if (lane == j) keep = r;
        }
        if (lane < 18) g_off[(size_t)(pg0 + p) * 18 + lane] = keep + off_b[lane];
    }
}

// ---------------------------------------------------------------------------
// Fused deform conv via mma.sync m16n8k8 TF32 (3-pass split for fp32 accuracy)
// Block: 128 px (M) x 128 out (N), 256 threads = 8 warps (2M x 4N).
// Warp tile M64 x N32 = 4x4 mma tiles. K = 9 taps x 128 ch, K8 per mma.
// smem: As[128 px][132] (67.6KB) + Bs[128 n][132] (67.6KB) = 135KB.
// Epilogue reuses As region as sdc[px][132].
// ---------------------------------------------------------------------------
#define PITCH 132
#define FUSED_SMEM (2 * 128 * PITCH * 4)

__global__ __launch_bounds__(256, 1) void fused_kernel(
        const float* __restrict__ dc_b,
        const float* __restrict__ ln_g,
        const float* __restrict__ ln_b,
        float* __restrict__ out) {
    extern __shared__ float smf[];
    float* As = smf;                    // [px][PITCH]
    float* Bs = smf + 128 * PITCH;      // [n][PITCH]

    int t = threadIdx.x;
    int w = t >> 5, l = t & 31;
    int m0 = blockIdx.x * 128;
    int b  = m0 / HW;
    int s0 = m0 - b * HW;
    const float* img = g_dsc + (size_t)b * HW * 128;

    int mbase = (w & 1) * 64;           // warp M offset
    int nbase = (w >> 1) * 32;          // warp N offset
    int qr = l >> 2;                    // quad row 0..7
    int qc = l & 3;                     // quad col 0..3
    int c0 = 4 * l;

    float d[4][4][4];
#pragma unroll
    for (int i = 0; i < 4; i++)
#pragma unroll
        for (int j = 0; j < 4; j++)
#pragma unroll
            for (int q = 0; q < 4; q++) d[i][j][q] = 0.f;

    for (int tap = 0; tap < 9; tap++) {
        __syncthreads();   // previous tap's tiles fully consumed

        // ---- gather tap into As: warp = 16 px, lane = 4 channels ----
        {
            int dy = tap / 3 - 1, dx = tap % 3 - 1;
#pragma unroll 2
            for (int ii = 0; ii < 16; ii++) {
                int px = w * 16 + ii;
                int s  = s0 + px;
                int y  = s / Wc, xw = s - y * Wc;
                float2 o = *(const float2*)&g_off[(size_t)(m0 + px) * 18 + 2 * tap];
                float ys = (float)(y + dy) + o.x;
                float xs = (float)(xw + dx) + o.y;
                float y0f = floorf(ys), x0f = floorf(xs);
                float wy = ys - y0f, wx = xs - x0f;
                int y0i = (int)y0f, x0i = (int)x0f;
                int y1i = y0i + 1, x1i = x0i + 1;
                float w00 = (1.f - wy) * (1.f - wx);
                float w01 = (1.f - wy) * wx;
                float w10 = wy * (1.f - wx);
                float w11 = wy * wx;
                bool vy0 = (unsigned)y0i < (unsigned)Hc;
                bool vy1 = (unsigned)y1i < (unsigned)Hc;
                bool vx0 = (unsigned)x0i < (unsigned)Wc;
                bool vx1 = (unsigned)x1i < (unsigned)Wc;
                if (!(vy0 && vx0)) w00 = 0.f;
                if (!(vy0 && vx1)) w01 = 0.f;
                if (!(vy1 && vx0)) w10 = 0.f;
                if (!(vy1 && vx1)) w11 = 0.f;
                int yc0 = min(Hc - 1, max(0, y0i));
                int yc1 = min(Hc - 1, max(0, y1i));
                int xc0 = min(Wc - 1, max(0, x0i));
                int xc1 = min(Wc - 1, max(0, x1i));
                float4 v00 = *(const float4*)&img[(size_t)(yc0 * Wc + xc0) * 128 + c0];
                float4 v01 = *(const float4*)&img[(size_t)(yc0 * Wc + xc1) * 128 + c0];
                float4 v10 = *(const float4*)&img[(size_t)(yc1 * Wc + xc0) * 128 + c0];
                float4 v11 = *(const float4*)&img[(size_t)(yc1 * Wc + xc1) * 128 + c0];
                float4 r;
                r.x = w00 * v00.x + w01 * v01.x + w10 * v10.x + w11 * v11.x;
                r.y = w00 * v00.y + w01 * v01.y + w10 * v10.y + w11 * v11.y;
                r.z = w00 * v00.z + w01 * v01.z + w10 * v10.z + w11 * v11.z;
                r.w = w00 * v00.w + w01 * v01.w + w10 * v10.w + w11 * v11.w;
                *(float4*)&As[px * PITCH + c0] = r;
            }
        }

        // ---- copy B tap into Bs[n][PITCH] ----
        {
            const float4* src = (const float4*)(g_wB + (tap << 14));
#pragma unroll
            for (int j = 0; j < 16; j++) {
                int f4 = t + j * 256;          // 0..4095
                int n = f4 >> 5, c4 = (f4 & 31) << 2;
                *(float4*)&Bs[n * PITCH + c4] = src[f4];
            }
        }
        __syncthreads();

        // ---- 16 K8-steps of TF32x3 mma ----
#pragma unroll 4
        for (int s = 0; s < 16; s++) {
            int k0 = s * 8;
            // A fragments (hi/lo) for 4 M-tiles
            uint32_t ah[4][4], al[4][4];
#pragma unroll
            for (int mi = 0; mi < 4; mi++) {
                int r0 = (mbase + mi * 16 + qr) * PITCH + k0 + qc;
                int r1 = r0 + 8 * PITCH;
                float f0 = As[r0], f1 = As[r1], f2 = As[r0 + 4], f3 = As[r1 + 4];
                ah[mi][0] = tf32r(f0);
                ah[mi][1] = tf32r(f1);
                ah[mi][2] = tf32r(f2);
                ah[mi][3] = tf32r(f3);
                al[mi][0] = __float_as_uint(f0 - __uint_as_float(ah[mi][0]));
                al[mi][1] = __float_as_uint(f1 - __uint_as_float(ah[mi][1]));
                al[mi][2] = __float_as_uint(f2 - __uint_as_float(ah[mi][2]));
                al[mi][3] = __float_as_uint(f3 - __uint_as_float(ah[mi][3]));
            }
            // B fragments (hi/lo) for 4 N-tiles
            uint32_t bh[4][2], bl[4][2];
#pragma unroll
            for (int ni = 0; ni < 4; ni++) {
                int nb = (nbase + ni * 8 + qr) * PITCH + k0 + qc;
                float f0 = Bs[nb], f1 = Bs[nb + 4];
                bh[ni][0] = tf32r(f0);
                bh[ni][1] = tf32r(f1);
                bl[ni][0] = __float_as_uint(f0 - __uint_as_float(bh[ni][0]));
                bl[ni][1] = __float_as_uint(f1 - __uint_as_float(bh[ni][1]));
            }
#pragma unroll
            for (int mi = 0; mi < 4; mi++)
#pragma unroll
                for (int ni = 0; ni < 4; ni++) {
                    MMA_TF32(d[mi][ni], ah[mi], bh[ni][0], bh[ni][1]);
                    MMA_TF32(d[mi][ni], ah[mi], bl[ni][0], bl[ni][1]);
                    MMA_TF32(d[mi][ni], al[mi], bh[ni][0], bh[ni][1]);
                }
        }
    }

    // ---- epilogue: bias + stage into sdc[px][PITCH] ----
    __syncthreads();
    float* sdc = smf;   // reuse As region
#pragma unroll
    for (int mi = 0; mi < 4; mi++) {
        int row0 = mbase + mi * 16 + qr;
#pragma unroll
        for (int ni = 0; ni < 4; ni++) {
            int col = nbase + ni * 8 + 2 * qc;
            float b0 = dc_b[col], b1 = dc_b[col + 1];
            float2 lo, hi;
            lo.x = d[mi][ni][0] + b0; lo.y = d[mi][ni][1] + b1;
            hi.x = d[mi][ni][2] + b0; hi.y = d[mi][ni][3] + b1;
            *(float2*)&sdc[row0 * PITCH + col]       = lo;
            *(float2*)&sdc[(row0 + 8) * PITCH + col] = hi;
        }
    }
    __syncthreads();

    // ---- LayerNorm(C) + sigmoid gate: warp-per-pixel, in place ----
    {
        float4 gv = *(const float4*)&ln_g[c0];
        float4 bv = *(const float4*)&ln_b[c0];
#pragma unroll 1
        for (int ii = 0; ii < 16; ii++) {
            int px = w * 16 + ii;
            int pg = m0 + px;
            float4 dd = *(const float4*)&sdc[px * PITCH + c0];
            float s  = dd.x + dd.y + dd.z + dd.w;
            float s2 = dd.x * dd.x + dd.y * dd.y + dd.z * dd.z + dd.w * dd.w;
#pragma unroll
            for (int o = 16; o; o >>= 1) {
                s  += __shfl_xor_sync(0xffffffffu, s,  o);
                s2 += __shfl_xor_sync(0xffffffffu, s2, o);
            }
            float mean = s * (1.f / 128.f);
            float var  = s2 * (1.f / 128.f) - mean * mean;
            float rstd = rsqrtf(var + 1e-5f);
            float4 ds = *(const float4*)&g_dsc[(size_t)pg * 128 + c0];
            float a;
            float4 r;
            a = (dd.x - mean) * rstd * gv.x + bv.x; r.x = ds.x / (1.f + expf(-a));
            a = (dd.y - mean) * rstd * gv.y + bv.y; r.y = ds.y / (1.f + expf(-a));
            a = (dd.z - mean) * rstd * gv.z + bv.z; r.z = ds.z / (1.f + expf(-a));
            a = (dd.w - mean) * rstd * gv.w + bv.w; r.w = ds.w / (1.f + expf(-a));
            *(float4*)&sdc[px * PITCH + c0] = r;
        }
    }
    __syncthreads();

    // ---- transpose-out: sdc[px][c] -> NCHW, coalesced ----
    {
        float* obase = out + (size_t)b * 128 * HW + s0;
#pragma unroll 1
        for (int j = 0; j < 64; j++) {
            int flat = t + j * 256;
            int c = flat >> 7, px = flat & 127;
            obase[(size_t)c * HW + px] = sdc[px * PITCH + c];
        }
    }
}

// ---------------------------------------------------------------------------
extern "C" void kernel_launch(void* const* d_in, const int* in_sizes, int n_in,
                              void* d_out, int out_size) {
    const float* x     = (const float*)d_in[0];
    const float* dw_w  = (const float*)d_in[1];
    const float* dw_b  = (const float*)d_in[2];
    const float* pw_w  = (const float*)d_in[3];
    const float* pw_b  = (const float*)d_in[4];
    const float* off_w = (const float*)d_in[5];
    const float* off_b = (const float*)d_in[6];
    const float* dc_w  = (const float*)d_in[7];
    const float* dc_b  = (const float*)d_in[8];
    const float* ln_g  = (const float*)d_in[9];
    const float* ln_b  = (const float*)d_in[10];
    float* out = (float*)d_out;

    cudaFuncSetAttribute(off_kernel, cudaFuncAttributeMaxDynamicSharedMemorySize,
                         9 * 18 * 128 * 4);
    cudaFuncSetAttribute(fused_kernel, cudaFuncAttributeMaxDynamicSharedMemorySize,
                         FUSED_SMEM);

    prep_kernel<<<576, 256>>>(dc_w, pw_w, off_w);
    dw_kernel<<<18432, 256>>>(x, dw_w, dw_b);
    pw_kernel<<<1152, 256>>>(pw_b);
    stats_kernel<<<384, 128>>>();
    mr_kernel<<<2, 256>>>();
    norm_kernel<<<18432, 256>>>();
    off_kernel<<<1152, 256, 9 * 18 * 128 * 4>>>(off_b);
    fused_kernel<<<288, 256, FUSED_SMEM>>>(dc_b, ln_g, ln_b, out);
}

// round 12
// speedup vs baseline: 2.0562x; 1.0873x over previous
#include <cuda_runtime.h>
#include <cstdint>

// ---------------------------------------------------------------------------
// DASAttentionGate. B=4, C=O=128, H=W=96, fp32.
// [dw3x3+pw1x1+stats fused] -> InstNorm apply -> offconv3x3 ->
//   [fused: per-tap bilinear gather -> mma.sync TF32x3 -> LN -> sigmoid gate]
// ---------------------------------------------------------------------------

#define Cc   128
#define Hc   96
#define Wc   96
#define HW   9216
#define PIX  36864

__device__ float g_h2[PIX * Cc];          // pw out, NHWC
__device__ float g_dsc[PIX * Cc];         // instance-normed, NHWC
__device__ float g_stats[1024];
__device__ float g_mr[1024];
__device__ float g_off[PIX * 18];
__device__ float g_offwT[9 * 18 * 128];
__device__ float g_pwT[128 * 128];
__device__ float g_wB[9 * 16384];         // deform weights per tap: [n*128+c]

// -------------------- TF32 helpers ------------------------------------------
__device__ __forceinline__ uint32_t tf32r(float v) {
    uint32_t r;
    asm("cvt.rna.tf32.f32 %0, %1;" : "=r"(r) : "f"(v));
    return r;
}

#define MMA_TF32(D, A, B0, B1)                                              \
    asm volatile("mma.sync.aligned.m16n8k8.row.col.f32.tf32.tf32.f32 "      \
        "{%0,%1,%2,%3}, {%4,%5,%6,%7}, {%8,%9}, {%0,%1,%2,%3};"             \
        : "+f"((D)[0]), "+f"((D)[1]), "+f"((D)[2]), "+f"((D)[3])            \
        : "r"((A)[0]), "r"((A)[1]), "r"((A)[2]), "r"((A)[3]),               \
          "r"(B0), "r"(B1))

// -------------------- prep: weight images + zero stats ----------------------
__global__ void prep_kernel(const float* __restrict__ dc_w,
                            const float* __restrict__ pw_w,
                            const float* __restrict__ off_w) {
    int i = blockIdx.x * blockDim.x + threadIdx.x;
    if (i < 9 * 16384) {
        int tap = i >> 14;
        int r   = i & 16383;
        int n   = r >> 7, c = r & 127;
        g_wB[i] = dc_w[(n * 128 + c) * 9 + tap];
    }
    if (i < 128 * 128) {
        int c = i >> 7, o = i & 127;
        g_pwT[i] = pw_w[o * 128 + c];
    }
    if (i < 9 * 18 * 128) {
        int k = i / 2304;
        int r = i - k * 2304;
        int j = r >> 7, c = r & 127;
        g_offwT[i] = off_w[(j * 128 + c) * 9 + k];
    }
    if (i < 1024) g_stats[i] = 0.f;
}

// ---------------------------------------------------------------------------
// Fused depthwise 3x3 + pointwise 1x1 + InstanceNorm stats.
// Block = 32 pixels of one row, 256 threads.
// smem: xt[128][3][34] halo tile (52.2KB) + sS[128][32] dw result (16.4KB).
// ---------------------------------------------------------------------------
#define DWPW_SMEM ((13056 + 4096) * 4)

__global__ __launch_bounds__(256) void dwpw_kernel(
        const float* __restrict__ x,
        const float* __restrict__ dw_w,
        const float* __restrict__ dw_b,
        const float* __restrict__ pw_b) {
    extern __shared__ float smd[];
    float* xt = smd;            // [c][r][34], c*102 + r*34 + col
    float* sS = smd + 13056;    // [c][32]

    int t  = threadIdx.x;
    int p0 = blockIdx.x * 32;
    int b  = p0 / HW;
    int s0 = p0 - b * HW;
    int y  = s0 / Wc;
    int x0 = s0 - y * Wc;

    // ---- halo load ----
    for (int f = t; f < 13056; f += 256) {
        int c   = f / 102;
        int rem = f - c * 102;
        int r   = rem / 34;
        int col = rem - r * 34;
        int yy = y + r - 1, xx = x0 + col - 1;
        float v = 0.f;
        if ((unsigned)yy < Hc && (unsigned)xx < Wc)
            v = x[(size_t)(b * 128 + c) * HW + yy * Wc + xx];
        xt[f] = v;
    }
    __syncthreads();

    // ---- depthwise: thread = (c = t>>1, 16 px) ----
    {
        int c   = t >> 1;
        int pxb = (t & 1) * 16;
        float wv[9];
#pragma unroll
        for (int j = 0; j < 9; j++) wv[j] = dw_w[c * 9 + j];
        float bias = dw_b[c];
        float accd[16];
#pragma unroll
        for (int p = 0; p < 16; p++) accd[p] = bias;
#pragma unroll
        for (int r = 0; r < 3; r++)
#pragma unroll
            for (int cc = 0; cc < 3; cc++) {
                float wgt = wv[r * 3 + cc];
                const float* src = &xt[c * 102 + r * 34 + pxb + cc];
#pragma unroll
                for (int p = 0; p < 16; p++) accd[p] += wgt * src[p];
            }
#pragma unroll
        for (int p = 0; p < 16; p++) sS[c * 32 + pxb + p] = accd[p];
    }
    __syncthreads();

    // ---- pointwise GEMM 32px x 128o + stats ----
    int px0 = (t & 7) * 4;
    int o0  = (t >> 3) * 4;
    float acc[4][4];
#pragma unroll
    for (int p = 0; p < 4; p++)
#pragma unroll
        for (int q = 0; q < 4; q++) acc[p][q] = 0.f;
#pragma unroll 4
    for (int c = 0; c < 128; c++) {
        float4 sv = *(const float4*)&sS[c * 32 + px0];
        float4 wv = __ldg((const float4*)&g_pwT[c * 128 + o0]);
        float sm[4] = {sv.x, sv.y, sv.z, sv.w};
        float wm[4] = {wv.x, wv.y, wv.z, wv.w};
#pragma unroll
        for (int p = 0; p < 4; p++)
#pragma unroll
            for (int q = 0; q < 4; q++) acc[p][q] += sm[p] * wm[q];
    }
    float sp[4], sq[4];
#pragma unroll
    for (int q = 0; q < 4; q++) { sp[q] = 0.f; sq[q] = 0.f; }
#pragma unroll
    for (int p = 0; p < 4; p++) {
        float4 o;
        o.x = acc[p][0] + pw_b[o0];
        o.y = acc[p][1] + pw_b[o0 + 1];
        o.z = acc[p][2] + pw_b[o0 + 2];
        o.w = acc[p][3] + pw_b[o0 + 3];
        sp[0] += o.x; sq[0] += o.x * o.x;
        sp[1] += o.y; sq[1] += o.y * o.y;
        sp[2] += o.z; sq[2] += o.z * o.z;
        sp[3] += o.w; sq[3] += o.w * o.w;
        *(float4*)&g_h2[(size_t)(p0 + px0 + p) * 128 + o0] = o;
    }
    // reduce over the 8 threads sharing o0 (consecutive lanes, xor 1/2/4)
#pragma unroll
    for (int q = 0; q < 4; q++) {
#pragma unroll
        for (int o = 1; o < 8; o <<= 1) {
            sp[q] += __shfl_xor_sync(0xffffffffu, sp[q], o);
            sq[q] += __shfl_xor_sync(0xffffffffu, sq[q], o);
        }
    }
    if ((t & 7) == 0) {
#pragma unroll
        for (int q = 0; q < 4; q++) {
            atomicAdd(&g_stats[b * 128 + o0 + q], sp[q]);
            atomicAdd(&g_stats[512 + b * 128 + o0 + q], sq[q]);
        }
    }
}

// -------------------- instance norm finalize + apply -------------------------
__global__ void mr_kernel() {
    int i = blockIdx.x * blockDim.x + threadIdx.x;
    if (i >= 512) return;
    float m = g_stats[i] * (1.f / HW);
    float v = g_stats[512 + i] * (1.f / HW) - m * m;
    g_mr[i] = m;
    g_mr[512 + i] = rsqrtf(v + 1e-5f);
}

__global__ void norm_kernel() {
    int i = blockIdx.x * blockDim.x + threadIdx.x;
    if (i >= PIX * Cc) return;
    int c  = i & 127;
    int pg = i >> 7;
    int b  = pg / HW;
    int bc = b * 128 + c;
    g_dsc[i] = (g_h2[i] - g_mr[bc]) * g_mr[512 + bc];
}

// -------------------- offset conv 3x3 (Cout=18) ------------------------------
__global__ __launch_bounds__(256) void off_kernel(const float* __restrict__ off_b) {
    extern __shared__ float w_s[];
    for (int i = threadIdx.x; i < 9 * 18 * 128; i += 256) w_s[i] = g_offwT[i];
    __syncthreads();

    int warp = threadIdx.x >> 5, lane = threadIdx.x & 31;
    int pg0  = blockIdx.x * 32 + warp * 4;
    int b    = pg0 / HW;
    const float* img = g_dsc + (size_t)b * HW * 128;
    int yb[4], xb[4];
#pragma unroll
    for (int p = 0; p < 4; p++) {
        int s = pg0 + p - b * HW;
        yb[p] = s / Wc; xb[p] = s % Wc;
    }
    int c0 = lane * 4;
    float acc[4][18];
#pragma unroll
    for (int p = 0; p < 4; p++)
#pragma unroll
        for (int j = 0; j < 18; j++) acc[p][j] = 0.f;

#pragma unroll
    for (int k = 0; k < 9; k++) {
        int dy = k / 3 - 1, dx = k % 3 - 1;
        float4 v[4];
#pragma unroll
        for (int p = 0; p < 4; p++) {
            int yy = yb[p] + dy, xx = xb[p] + dx;
            if ((unsigned)yy < Hc && (unsigned)xx < Wc)
                v[p] = *(const float4*)&img[(size_t)(yy * Wc + xx) * 128 + c0];
            else
                v[p] = make_float4(0.f, 0.f, 0.f, 0.f);
        }
        const float* wb = w_s + k * 2304;
#pragma unroll
        for (int j = 0; j < 18; j++) {
            float4 wv = *(const float4*)&wb[j * 128 + c0];
#pragma unroll
            for (int p = 0; p < 4; p++)
                acc[p][j] += wv.x * v[p].x + wv.y * v[p].y + wv.z * v[p].z + wv.w * v[p].w;
        }
    }
#pragma unroll
    for (int p = 0; p < 4; p++) {
        float keep = 0.f;
#pragma unroll
        for (int j = 0; j < 18; j++) {
            float r = acc[p][j];
            r += __shfl_xor_sync(0xffffffffu, r, 16);
            r += __shfl_xor_sync(0xffffffffu, r, 8);
            r += __shfl_xor_sync(0xffffffffu, r, 4);
            r += __shfl_xor_sync(0xffffffffu, r, 2);
            r += __shfl_xor_sync(0xffffffffu, r, 1);
            if (lane == j) keep = r;
        }
        if (lane < 18) g_off[(size_t)(pg0 + p) * 18 + lane] = keep + off_b[lane];
    }
}

// ---------------------------------------------------------------------------
// Fused deform conv via mma.sync m16n8k8 TF32x3.
// Block: 64 px (M) x 128 out (N), 256 threads = 8 warps (2M x 4N),
// warp tile M32 x N32 = 2x4 mma tiles. 2 CTAs/SM (101.4KB smem each) so
// one CTA's gather (L2-bound) overlaps the other's HMMA.
// smem: As[64 px][132] + Bs[128 n][132]; epilogue reuses As as sdc[64][132].
// ---------------------------------------------------------------------------
#define PITCH 132
#define FUSED_SMEM ((64 * PITCH + 128 * PITCH) * 4)

__global__ __launch_bounds__(256, 2) void fused_kernel(
        const float* __restrict__ dc_b,
        const float* __restrict__ ln_g,
        const float* __restrict__ ln_b,
        float* __restrict__ out) {
    extern __shared__ float smf[];
    float* As = smf;                    // [px][PITCH], 64 rows
    float* Bs = smf + 64 * PITCH;       // [n][PITCH], 128 rows

    int t = threadIdx.x;
    int w = t >> 5, l = t & 31;
    int m0 = blockIdx.x * 64;
    int b  = m0 / HW;
    int s0 = m0 - b * HW;
    const float* img = g_dsc + (size_t)b * HW * 128;

    int mbase = (w & 1) * 32;           // warp M offset
    int nbase = (w >> 1) * 32;          // warp N offset
    int qr = l >> 2;                    // 0..7
    int qc = l & 3;                     // 0..3
    int c0 = 4 * l;

    float d[2][4][4];
#pragma unroll
    for (int i = 0; i < 2; i++)
#pragma unroll
        for (int j = 0; j < 4; j++)
#pragma unroll
            for (int q = 0; q < 4; q++) d[i][j][q] = 0.f;

    for (int tap = 0; tap < 9; tap++) {
        __syncthreads();   // previous tap's tiles fully consumed

        // ---- gather tap into As: warp = 8 px, lane = 4 channels ----
        {
            int dy = tap / 3 - 1, dx = tap % 3 - 1;
#pragma unroll 2
            for (int ii = 0; ii < 8; ii++) {
                int px = w * 8 + ii;
                int s  = s0 + px;
                int y  = s / Wc, xw = s - y * Wc;
                float2 o = *(const float2*)&g_off[(size_t)(m0 + px) * 18 + 2 * tap];
                float ys = (float)(y + dy) + o.x;
                float xs = (float)(xw + dx) + o.y;
                float y0f = floorf(ys), x0f = floorf(xs);
                float wy = ys - y0f, wx = xs - x0f;
                int y0i = (int)y0f, x0i = (int)x0f;
                int y1i = y0i + 1, x1i = x0i + 1;
                float w00 = (1.f - wy) * (1.f - wx);
                float w01 = (1.f - wy) * wx;
                float w10 = wy * (1.f - wx);
                float w11 = wy * wx;
                bool vy0 = (unsigned)y0i < (unsigned)Hc;
                bool vy1 = (unsigned)y1i < (unsigned)Hc;
                bool vx0 = (unsigned)x0i < (unsigned)Wc;
                bool vx1 = (unsigned)x1i < (unsigned)Wc;
                if (!(vy0 && vx0)) w00 = 0.f;
                if (!(vy0 && vx1)) w01 = 0.f;
                if (!(vy1 && vx0)) w10 = 0.f;
                if (!(vy1 && vx1)) w11 = 0.f;
                int yc0 = min(Hc - 1, max(0, y0i));
                int yc1 = min(Hc - 1, max(0, y1i));
                int xc0 = min(Wc - 1, max(0, x0i));
                int xc1 = min(Wc - 1, max(0, x1i));
                float4 v00 = *(const float4*)&img[(size_t)(yc0 * Wc + xc0) * 128 + c0];
                float4 v01 = *(const float4*)&img[(size_t)(yc0 * Wc + xc1) * 128 + c0];
                float4 v10 = *(const float4*)&img[(size_t)(yc1 * Wc + xc0) * 128 + c0];
                float4 v11 = *(const float4*)&img[(size_t)(yc1 * Wc + xc1) * 128 + c0];
                float4 r;
                r.x = w00 * v00.x + w01 * v01.x + w10 * v10.x + w11 * v11.x;
                r.y = w00 * v00.y + w01 * v01.y + w10 * v10.y + w11 * v11.y;
                r.z = w00 * v00.z + w01 * v01.z + w10 * v10.z + w11 * v11.z;
                r.w = w00 * v00.w + w01 * v01.w + w10 * v10.w + w11 * v11.w;
                *(float4*)&As[px * PITCH + c0] = r;
            }
        }

        // ---- copy B tap into Bs[n][PITCH] ----
        {
            const float4* src = (const float4*)(g_wB + (tap << 14));
#pragma unroll
            for (int j = 0; j < 16; j++) {
                int f4 = t + j * 256;          // 0..4095
                int n = f4 >> 5, c4 = (f4 & 31) << 2;
                *(float4*)&Bs[n * PITCH + c4] = src[f4];
            }
        }
        __syncthreads();

        // ---- 16 K8-steps of TF32x3 mma ----
#pragma unroll 4
        for (int s = 0; s < 16; s++) {
            int k0 = s * 8;
            uint32_t ah[2][4], al[2][4];
#pragma unroll
            for (int mi = 0; mi < 2; mi++) {
                int r0 = (mbase + mi * 16 + qr) * PITCH + k0 + qc;
                int r1 = r0 + 8 * PITCH;
                float f0 = As[r0], f1 = As[r1], f2 = As[r0 + 4], f3 = As[r1 + 4];
                ah[mi][0] = tf32r(f0);
                ah[mi][1] = tf32r(f1);
                ah[mi][2] = tf32r(f2);
                ah[mi][3] = tf32r(f3);
                al[mi][0] = __float_as_uint(f0 - __uint_as_float(ah[mi][0]));
                al[mi][1] = __float_as_uint(f1 - __uint_as_float(ah[mi][1]));
                al[mi][2] = __float_as_uint(f2 - __uint_as_float(ah[mi][2]));
                al[mi][3] = __float_as_uint(f3 - __uint_as_float(ah[mi][3]));
            }
            uint32_t bh[4][2], bl[4][2];
#pragma unroll
            for (int ni = 0; ni < 4; ni++) {
                int nb = (nbase + ni * 8 + qr) * PITCH + k0 + qc;
                float f0 = Bs[nb], f1 = Bs[nb + 4];
                bh[ni][0] = tf32r(f0);
                bh[ni][1] = tf32r(f1);
                bl[ni][0] = __float_as_uint(f0 - __uint_as_float(bh[ni][0]));
                bl[ni][1] = __float_as_uint(f1 - __uint_as_float(bh[ni][1]));
            }
#pragma unroll
            for (int mi = 0; mi < 2; mi++)
#pragma unroll
                for (int ni = 0; ni < 4; ni++) {
                    MMA_TF32(d[mi][ni], ah[mi], bh[ni][0], bh[ni][1]);
                    MMA_TF32(d[mi][ni], ah[mi], bl[ni][0], bl[ni][1]);
                    MMA_TF32(d[mi][ni], al[mi], bh[ni][0], bh[ni][1]);
                }
        }
    }

    // ---- epilogue: bias + stage into sdc[px][PITCH] ----
    __syncthreads();
    float* sdc = smf;   // reuse As region
#pragma unroll
    for (int mi = 0; mi < 2; mi++) {
        int row0 = mbase + mi * 16 + qr;
#pragma unroll
        for (int ni = 0; ni < 4; ni++) {
            int col = nbase + ni * 8 + 2 * qc;
            float b0 = dc_b[col], b1 = dc_b[col + 1];
            float2 lo, hi;
            lo.x = d[mi][ni][0] + b0; lo.y = d[mi][ni][1] + b1;
            hi.x = d[mi][ni][2] + b0; hi.y = d[mi][ni][3] + b1;
            *(float2*)&sdc[row0 * PITCH + col]       = lo;
            *(float2*)&sdc[(row0 + 8) * PITCH + col] = hi;
        }
    }
    __syncthreads();

    // ---- LayerNorm(C) + sigmoid gate: warp-per-pixel, in place ----
    {
        float4 gv = *(const float4*)&ln_g[c0];
        float4 bv = *(const float4*)&ln_b[c0];
#pragma unroll 1
        for (int ii = 0; ii < 8; ii++) {
            int px = w * 8 + ii;
            int pg = m0 + px;
            float4 dd = *(const float4*)&sdc[px * PITCH + c0];
            float s  = dd.x + dd.y + dd.z + dd.w;
            float s2 = dd.x * dd.x + dd.y * dd.y + dd.z * dd.z + dd.w * dd.w;
#pragma unroll
            for (int o = 16; o; o >>= 1) {
                s  += __shfl_xor_sync(0xffffffffu, s,  o);
                s2 += __shfl_xor_sync(0xffffffffu, s2, o);
            }
            float mean = s * (1.f / 128.f);
            float var  = s2 * (1.f / 128.f) - mean * mean;
            float rstd = rsqrtf(var + 1e-5f);
            float4 ds = *(const float4*)&g_dsc[(size_t)pg * 128 + c0];
            float a;
            float4 r;
            a = (dd.x - mean) * rstd * gv.x + bv.x; r.x = ds.x / (1.f + expf(-a));
            a = (dd.y - mean) * rstd * gv.y + bv.y; r.y = ds.y / (1.f + expf(-a));
            a = (dd.z - mean) * rstd * gv.z + bv.z; r.z = ds.z / (1.f + expf(-a));
            a = (dd.w - mean) * rstd * gv.w + bv.w; r.w = ds.w / (1.f + expf(-a));
            *(float4*)&sdc[px * PITCH + c0] = r;
        }
    }
    __syncthreads();

    // ---- transpose-out: sdc[px][c] -> NCHW, coalesced ----
    {
        float* obase = out + (size_t)b * 128 * HW + s0;
#pragma unroll 1
        for (int j = 0; j < 32; j++) {
            int flat = t + j * 256;            // 0..8191
            int c = flat >> 6, px = flat & 63;
            obase[(size_t)c * HW + px] = sdc[px * PITCH + c];
        }
    }
}

// ---------------------------------------------------------------------------
extern "C" void kernel_launch(void* const* d_in, const int* in_sizes, int n_in,
                              void* d_out, int out_size) {
    const float* x     = (const float*)d_in[0];
    const float* dw_w  = (const float*)d_in[1];
    const float* dw_b  = (const float*)d_in[2];
    const float* pw_w  = (const float*)d_in[3];
    const float* pw_b  = (const float*)d_in[4];
    const float* off_w = (const float*)d_in[5];
    const float* off_b = (const float*)d_in[6];
    const float* dc_w  = (const float*)d_in[7];
    const float* dc_b  = (const float*)d_in[8];
    const float* ln_g  = (const float*)d_in[9];
    const float* ln_b  = (const float*)d_in[10];
    float* out = (float*)d_out;

    cudaFuncSetAttribute(dwpw_kernel, cudaFuncAttributeMaxDynamicSharedMemorySize,
                         DWPW_SMEM);
    cudaFuncSetAttribute(off_kernel, cudaFuncAttributeMaxDynamicSharedMemorySize,
                         9 * 18 * 128 * 4);
    cudaFuncSetAttribute(fused_kernel, cudaFuncAttributeMaxDynamicSharedMemorySize,
                         FUSED_SMEM);

    prep_kernel<<<576, 256>>>(dc_w, pw_w, off_w);
    dwpw_kernel<<<1152, 256, DWPW_SMEM>>>(x, dw_w, dw_b, pw_b);
    mr_kernel<<<2, 256>>>();
    norm_kernel<<<18432, 256>>>();
    off_kernel<<<1152, 256, 9 * 18 * 128 * 4>>>(off_b);
    fused_kernel<<<576, 256, FUSED_SMEM>>>(dc_b, ln_g, ln_b, out);
}

// round 13
// speedup vs baseline: 2.1036x; 1.0231x over previous
#include <cuda_runtime.h>
#include <cstdint>

// ---------------------------------------------------------------------------
// DASAttentionGate. B=4, C=O=128, H=W=96, fp32.
// [dw3x3+pw1x1+stats fused] -> mr -> offconv3x3 (norm on the fly) ->
//   [fused: gather(norm on the fly) -> mma.sync TF32x3 -> LN -> sigmoid gate]
// g_dsc / norm_kernel eliminated: instance-norm applied affinely by consumers.
// ---------------------------------------------------------------------------

#define Cc   128
#define Hc   96
#define Wc   96
#define HW   9216
#define PIX  36864

__device__ float g_h2[PIX * Cc];          // pw out, NHWC (pre-norm)
__device__ float g_stats[1024];
__device__ float g_mr[1024];              // mean[512], rstd[512]
__device__ float g_off[PIX * 18];
__device__ float g_offwT[9 * 18 * 128];
__device__ float g_pwT[128 * 128];
__device__ float g_wB[9 * 16384];         // deform weights per tap: [n*128+c]

// -------------------- TF32 helpers ------------------------------------------
__device__ __forceinline__ uint32_t tf32r(float v) {
    uint32_t r;
    asm("cvt.rna.tf32.f32 %0, %1;" : "=r"(r) : "f"(v));
    return r;
}

#define MMA_TF32(D, A, B0, B1)                                              \
    asm volatile("mma.sync.aligned.m16n8k8.row.col.f32.tf32.tf32.f32 "      \
        "{%0,%1,%2,%3}, {%4,%5,%6,%7}, {%8,%9}, {%0,%1,%2,%3};"             \
        : "+f"((D)[0]), "+f"((D)[1]), "+f"((D)[2]), "+f"((D)[3])            \
        : "r"((A)[0]), "r"((A)[1]), "r"((A)[2]), "r"((A)[3]),               \
          "r"(B0), "r"(B1))

// -------------------- prep: weight images + zero stats ----------------------
__global__ void prep_kernel(const float* __restrict__ dc_w,
                            const float* __restrict__ pw_w,
                            const float* __restrict__ off_w) {
    int i = blockIdx.x * blockDim.x + threadIdx.x;
    if (i < 9 * 16384) {
        int tap = i >> 14;
        int r   = i & 16383;
        int n   = r >> 7, c = r & 127;
        g_wB[i] = dc_w[(n * 128 + c) * 9 + tap];
    }
    if (i < 128 * 128) {
        int c = i >> 7, o = i & 127;
        g_pwT[i] = pw_w[o * 128 + c];
    }
    if (i < 9 * 18 * 128) {
        int k = i / 2304;
        int r = i - k * 2304;
        int j = r >> 7, c = r & 127;
        g_offwT[i] = off_w[(j * 128 + c) * 9 + k];
    }
    if (i < 1024) g_stats[i] = 0.f;
}

// ---------------------------------------------------------------------------
// Fused depthwise 3x3 + pointwise 1x1 + InstanceNorm stats.
// Block = 32 pixels of one row, 256 threads.
// ---------------------------------------------------------------------------
#define DWPW_SMEM ((13056 + 4096) * 4)

__global__ __launch_bounds__(256) void dwpw_kernel(
        const float* __restrict__ x,
        const float* __restrict__ dw_w,
        const float* __restrict__ dw_b,
        const float* __restrict__ pw_b) {
    extern __shared__ float smd[];
    float* xt = smd;            // [c][r][34]
    float* sS = smd + 13056;    // [c][32]

    int t  = threadIdx.x;
    int p0 = blockIdx.x * 32;
    int b  = p0 / HW;
    int s0 = p0 - b * HW;
    int y  = s0 / Wc;
    int x0 = s0 - y * Wc;

    for (int f = t; f < 13056; f += 256) {
        int c   = f / 102;
        int rem = f - c * 102;
        int r   = rem / 34;
        int col = rem - r * 34;
        int yy = y + r - 1, xx = x0 + col - 1;
        float v = 0.f;
        if ((unsigned)yy < Hc && (unsigned)xx < Wc)
            v = x[(size_t)(b * 128 + c) * HW + yy * Wc + xx];
        xt[f] = v;
    }
    __syncthreads();

    {
        int c   = t >> 1;
        int pxb = (t & 1) * 16;
        float wv[9];
#pragma unroll
        for (int j = 0; j < 9; j++) wv[j] = dw_w[c * 9 + j];
        float bias = dw_b[c];
        float accd[16];
#pragma unroll
        for (int p = 0; p < 16; p++) accd[p] = bias;
#pragma unroll
        for (int r = 0; r < 3; r++)
#pragma unroll
            for (int cc = 0; cc < 3; cc++) {
                float wgt = wv[r * 3 + cc];
                const float* src = &xt[c * 102 + r * 34 + pxb + cc];
#pragma unroll
                for (int p = 0; p < 16; p++) accd[p] += wgt * src[p];
            }
#pragma unroll
        for (int p = 0; p < 16; p++) sS[c * 32 + pxb + p] = accd[p];
    }
    __syncthreads();

    int px0 = (t & 7) * 4;
    int o0  = (t >> 3) * 4;
    float acc[4][4];
#pragma unroll
    for (int p = 0; p < 4; p++)
#pragma unroll
        for (int q = 0; q < 4; q++) acc[p][q] = 0.f;
#pragma unroll 4
    for (int c = 0; c < 128; c++) {
        float4 sv = *(const float4*)&sS[c * 32 + px0];
        float4 wv = __ldg((const float4*)&g_pwT[c * 128 + o0]);
        float sm[4] = {sv.x, sv.y, sv.z, sv.w};
        float wm[4] = {wv.x, wv.y, wv.z, wv.w};
#pragma unroll
        for (int p = 0; p < 4; p++)
#pragma unroll
            for (int q = 0; q < 4; q++) acc[p][q] += sm[p] * wm[q];
    }
    float sp[4], sq[4];
#pragma unroll
    for (int q = 0; q < 4; q++) { sp[q] = 0.f; sq[q] = 0.f; }
#pragma unroll
    for (int p = 0; p < 4; p++) {
        float4 o;
        o.x = acc[p][0] + pw_b[o0];
        o.y = acc[p][1] + pw_b[o0 + 1];
        o.z = acc[p][2] + pw_b[o0 + 2];
        o.w = acc[p][3] + pw_b[o0 + 3];
        sp[0] += o.x; sq[0] += o.x * o.x;
        sp[1] += o.y; sq[1] += o.y * o.y;
        sp[2] += o.z; sq[2] += o.z * o.z;
        sp[3] += o.w; sq[3] += o.w * o.w;
        *(float4*)&g_h2[(size_t)(p0 + px0 + p) * 128 + o0] = o;
    }
#pragma unroll
    for (int q = 0; q < 4; q++) {
#pragma unroll
        for (int o = 1; o < 8; o <<= 1) {
            sp[q] += __shfl_xor_sync(0xffffffffu, sp[q], o);
            sq[q] += __shfl_xor_sync(0xffffffffu, sq[q], o);
        }
    }
    if ((t & 7) == 0) {
#pragma unroll
        for (int q = 0; q < 4; q++) {
            atomicAdd(&g_stats[b * 128 + o0 + q], sp[q]);
            atomicAdd(&g_stats[512 + b * 128 + o0 + q], sq[q]);
        }
    }
}

// -------------------- instance norm finalize ---------------------------------
__global__ void mr_kernel() {
    int i = blockIdx.x * blockDim.x + threadIdx.x;
    if (i >= 512) return;
    float m = g_stats[i] * (1.f / HW);
    float v = g_stats[512 + i] * (1.f / HW) - m * m;
    g_mr[i] = m;
    g_mr[512 + i] = rsqrtf(v + 1e-5f);
}

// -------------------- offset conv 3x3 (Cout=18), norm on the fly -------------
__global__ __launch_bounds__(256) void off_kernel(const float* __restrict__ off_b) {
    extern __shared__ float w_s[];
    for (int i = threadIdx.x; i < 9 * 18 * 128; i += 256) w_s[i] = g_offwT[i];
    __syncthreads();

    int warp = threadIdx.x >> 5, lane = threadIdx.x & 31;
    int pg0  = blockIdx.x * 32 + warp * 4;
    int b    = pg0 / HW;
    const float* img = g_h2 + (size_t)b * HW * 128;
    int c0 = lane * 4;
    float4 m4 = *(const float4*)&g_mr[b * 128 + c0];
    float4 r4 = *(const float4*)&g_mr[512 + b * 128 + c0];

    int yb[4], xb[4];
#pragma unroll
    for (int p = 0; p < 4; p++) {
        int s = pg0 + p - b * HW;
        yb[p] = s / Wc; xb[p] = s % Wc;
    }
    float acc[4][18];
#pragma unroll
    for (int p = 0; p < 4; p++)
#pragma unroll
        for (int j = 0; j < 18; j++) acc[p][j] = 0.f;

#pragma unroll
    for (int k = 0; k < 9; k++) {
        int dy = k / 3 - 1, dx = k % 3 - 1;
        float4 v[4];
#pragma unroll
        for (int p = 0; p < 4; p++) {
            int yy = yb[p] + dy, xx = xb[p] + dx;
            if ((unsigned)yy < Hc && (unsigned)xx < Wc) {
                float4 raw = *(const float4*)&img[(size_t)(yy * Wc + xx) * 128 + c0];
                v[p].x = (raw.x - m4.x) * r4.x;
                v[p].y = (raw.y - m4.y) * r4.y;
                v[p].z = (raw.z - m4.z) * r4.z;
                v[p].w = (raw.w - m4.w) * r4.w;
            } else {
                v[p] = make_float4(0.f, 0.f, 0.f, 0.f);
            }
        }
        const float* wb = w_s + k * 2304;
#pragma unroll
        for (int j = 0; j < 18; j++) {
            float4 wv = *(const float4*)&wb[j * 128 + c0];
#pragma unroll
            for (int p = 0; p < 4; p++)
                acc[p][j] += wv.x * v[p].x + wv.y * v[p].y + wv.z * v[p].z + wv.w * v[p].w;
        }
    }
#pragma unroll
    for (int p = 0; p < 4; p++) {
        float keep = 0.f;
#pragma unroll
        for (int j = 0; j < 18; j++) {
            float r = acc[p][j];
            r += __shfl_xor_sync(0xffffffffu, r, 16);
            r += __shfl_xor_sync(0xffffffffu, r, 8);
            r += __shfl_xor_sync(0xffffffffu, r, 4);
            r += __shfl_xor_sync(0xffffffffu, r, 2);
            r += __shfl_xor_sync(0xffffffffu, r, 1);
            if (lane == j) keep = r;
        }
        if (lane < 18) g_off[(size_t)(pg0 + p) * 18 + lane] = keep + off_b[lane];
    }
}

// ---------------------------------------------------------------------------
// Fused deform conv via mma.sync m16n8k8 TF32x3, norm folded into gather.
// Block: 64 px (M) x 128 out (N), 256 threads = 8 warps (2M x 4N), 2 CTAs/SM.
// ---------------------------------------------------------------------------
#define PITCH 132
#define FUSED_SMEM ((64 * PITCH + 128 * PITCH) * 4)

__global__ __launch_bounds__(256, 2) void fused_kernel(
        const float* __restrict__ dc_b,
        const float* __restrict__ ln_g,
        const float* __restrict__ ln_b,
        float* __restrict__ out) {
    extern __shared__ float smf[];
    float* As = smf;                    // [px][PITCH], 64 rows
    float* Bs = smf + 64 * PITCH;       // [n][PITCH], 128 rows

    int t = threadIdx.x;
    int w = t >> 5, l = t & 31;
    int m0 = blockIdx.x * 64;
    int b  = m0 / HW;
    int s0 = m0 - b * HW;
    const float* img = g_h2 + (size_t)b * HW * 128;

    int mbase = (w & 1) * 32;
    int nbase = (w >> 1) * 32;
    int qr = l >> 2;
    int qc = l & 3;
    int c0 = 4 * l;

    float4 m4 = *(const float4*)&g_mr[b * 128 + c0];
    float4 r4 = *(const float4*)&g_mr[512 + b * 128 + c0];

    float d[2][4][4];
#pragma unroll
    for (int i = 0; i < 2; i++)
#pragma unroll
        for (int j = 0; j < 4; j++)
#pragma unroll
            for (int q = 0; q < 4; q++) d[i][j][q] = 0.f;

    for (int tap = 0; tap < 9; tap++) {
        __syncthreads();

        // ---- gather tap into As (normalized on the fly via wsum trick) ----
        {
            int dy = tap / 3 - 1, dx = tap % 3 - 1;
#pragma unroll 2
            for (int ii = 0; ii < 8; ii++) {
                int px = w * 8 + ii;
                int s  = s0 + px;
                int y  = s / Wc, xw = s - y * Wc;
                float2 o = *(const float2*)&g_off[(size_t)(m0 + px) * 18 + 2 * tap];
                float ys = (float)(y + dy) + o.x;
                float xs = (float)(xw + dx) + o.y;
                float y0f = floorf(ys), x0f = floorf(xs);
                float wy = ys - y0f, wx = xs - x0f;
                int y0i = (int)y0f, x0i = (int)x0f;
                int y1i = y0i + 1, x1i = x0i + 1;
                float w00 = (1.f - wy) * (1.f - wx);
                float w01 = (1.f - wy) * wx;
                float w10 = wy * (1.f - wx);
                float w11 = wy * wx;
                bool vy0 = (unsigned)y0i < (unsigned)Hc;
                bool vy1 = (unsigned)y1i < (unsigned)Hc;
                bool vx0 = (unsigned)x0i < (unsigned)Wc;
                bool vx1 = (unsigned)x1i < (unsigned)Wc;
                if (!(vy0 && vx0)) w00 = 0.f;
                if (!(vy0 && vx1)) w01 = 0.f;
                if (!(vy1 && vx0)) w10 = 0.f;
                if (!(vy1 && vx1)) w11 = 0.f;
                float wsum = w00 + w01 + w10 + w11;
                int yc0 = min(Hc - 1, max(0, y0i));
                int yc1 = min(Hc - 1, max(0, y1i));
                int xc0 = min(Wc - 1, max(0, x0i));
                int xc1 = min(Wc - 1, max(0, x1i));
                float4 v00 = *(const float4*)&img[(size_t)(yc0 * Wc + xc0) * 128 + c0];
                float4 v01 = *(const float4*)&img[(size_t)(yc0 * Wc + xc1) * 128 + c0];
                float4 v10 = *(const float4*)&img[(size_t)(yc1 * Wc + xc0) * 128 + c0];
                float4 v11 = *(const float4*)&img[(size_t)(yc1 * Wc + xc1) * 128 + c0];
                float4 r;
                r.x = w00 * v00.x + w01 * v01.x + w10 * v10.x + w11 * v11.x;
                r.y = w00 * v00.y + w01 * v01.y + w10 * v10.y + w11 * v11.y;
                r.z = w00 * v00.z + w01 * v01.z + w10 * v10.z + w11 * v11.z;
                r.w = w00 * v00.w + w01 * v01.w + w10 * v10.w + w11 * v11.w;
                // normalized: (acc - m*wsum) * r
                r.x = (r.x - m4.x * wsum) * r4.x;
                r.y = (r.y - m4.y * wsum) * r4.y;
                r.z = (r.z - m4.z * wsum) * r4.z;
                r.w = (r.w - m4.w * wsum) * r4.w;
                *(float4*)&As[px * PITCH + c0] = r;
            }
        }

        // ---- copy B tap into Bs[n][PITCH] ----
        {
            const float4* src = (const float4*)(g_wB + (tap << 14));
#pragma unroll
            for (int j = 0; j < 16; j++) {
                int f4 = t + j * 256;
                int n = f4 >> 5, c4 = (f4 & 31) << 2;
                *(float4*)&Bs[n * PITCH + c4] = src[f4];
            }
        }
        __syncthreads();

        // ---- 16 K8-steps of TF32x3 mma ----
#pragma unroll 4
        for (int s = 0; s < 16; s++) {
            int k0 = s * 8;
            uint32_t ah[2][4], al[2][4];
#pragma unroll
            for (int mi = 0; mi < 2; mi++) {
                int r0 = (mbase + mi * 16 + qr) * PITCH + k0 + qc;
                int r1 = r0 + 8 * PITCH;
                float f0 = As[r0], f1 = As[r1], f2 = As[r0 + 4], f3 = As[r1 + 4];
                ah[mi][0] = tf32r(f0);
                ah[mi][1] = tf32r(f1);
                ah[mi][2] = tf32r(f2);
                ah[mi][3] = tf32r(f3);
                al[mi][0] = __float_as_uint(f0 - __uint_as_float(ah[mi][0]));
                al[mi][1] = __float_as_uint(f1 - __uint_as_float(ah[mi][1]));
                al[mi][2] = __float_as_uint(f2 - __uint_as_float(ah[mi][2]));
                al[mi][3] = __float_as_uint(f3 - __uint_as_float(ah[mi][3]));
            }
            uint32_t bh[4][2], bl[4][2];
#pragma unroll
            for (int ni = 0; ni < 4; ni++) {
                int nb = (nbase + ni * 8 + qr) * PITCH + k0 + qc;
                float f0 = Bs[nb], f1 = Bs[nb + 4];
                bh[ni][0] = tf32r(f0);
                bh[ni][1] = tf32r(f1);
                bl[ni][0] = __float_as_uint(f0 - __uint_as_float(bh[ni][0]));
                bl[ni][1] = __float_as_uint(f1 - __uint_as_float(bh[ni][1]));
            }
#pragma unroll
            for (int mi = 0; mi < 2; mi++)
#pragma unroll
                for (int ni = 0; ni < 4; ni++) {
                    MMA_TF32(d[mi][ni], ah[mi], bh[ni][0], bh[ni][1]);
                    MMA_TF32(d[mi][ni], ah[mi], bl[ni][0], bl[ni][1]);
                    MMA_TF32(d[mi][ni], al[mi], bh[ni][0], bh[ni][1]);
                }
        }
    }

    // ---- epilogue: bias + stage into sdc[px][PITCH] ----
    __syncthreads();
    float* sdc = smf;
#pragma unroll
    for (int mi = 0; mi < 2; mi++) {
        int row0 = mbase + mi * 16 + qr;
#pragma unroll
        for (int ni = 0; ni < 4; ni++) {
            int col = nbase + ni * 8 + 2 * qc;
            float b0 = dc_b[col], b1 = dc_b[col + 1];
            float2 lo, hi;
            lo.x = d[mi][ni][0] + b0; lo.y = d[mi][ni][1] + b1;
            hi.x = d[mi][ni][2] + b0; hi.y = d[mi][ni][3] + b1;
            *(float2*)&sdc[row0 * PITCH + col]       = lo;
            *(float2*)&sdc[(row0 + 8) * PITCH + col] = hi;
        }
    }
    __syncthreads();

    // ---- LayerNorm(C) + sigmoid gate (gate reads g_h2 + on-the-fly norm) ----
    {
        float4 gv = *(const float4*)&ln_g[c0];
        float4 bv = *(const float4*)&ln_b[c0];
#pragma unroll 1
        for (int ii = 0; ii < 8; ii++) {
            int px = w * 8 + ii;
            int pg = m0 + px;
            float4 dd = *(const float4*)&sdc[px * PITCH + c0];
            float s  = dd.x + dd.y + dd.z + dd.w;
            float s2 = dd.x * dd.x + dd.y * dd.y + dd.z * dd.z + dd.w * dd.w;
#pragma unroll
            for (int o = 16; o; o >>= 1) {
                s  += __shfl_xor_sync(0xffffffffu, s,  o);
                s2 += __shfl_xor_sync(0xffffffffu, s2, o);
            }
            float mean = s * (1.f / 128.f);
            float var  = s2 * (1.f / 128.f) - mean * mean;
            float rstd = rsqrtf(var + 1e-5f);
            float4 raw = *(const float4*)&g_h2[(size_t)pg * 128 + c0];
            float4 ds;
            ds.x = (raw.x - m4.x) * r4.x;
            ds.y = (raw.y - m4.y) * r4.y;
            ds.z = (raw.z - m4.z) * r4.z;
            ds.w = (raw.w - m4.w) * r4.w;
            float a;
            float4 r;
            a = (dd.x - mean) * rstd * gv.x + bv.x; r.x = ds.x / (1.f + expf(-a));
            a = (dd.y - mean) * rstd * gv.y + bv.y; r.y = ds.y / (1.f + expf(-a));
            a = (dd.z - mean) * rstd * gv.z + bv.z; r.z = ds.z / (1.f + expf(-a));
            a = (dd.w - mean) * rstd * gv.w + bv.w; r.w = ds.w / (1.f + expf(-a));
            *(float4*)&sdc[px * PITCH + c0] = r;
        }
    }
    __syncthreads();

    // ---- transpose-out: sdc[px][c] -> NCHW, coalesced ----
    {
        float* obase = out + (size_t)b * 128 * HW + s0;
#pragma unroll 1
        for (int j = 0; j < 32; j++) {
            int flat = t + j * 256;
            int c = flat >> 6, px = flat & 63;
            obase[(size_t)c * HW + px] = sdc[px * PITCH + c];
        }
    }
}

// ---------------------------------------------------------------------------
extern "C" void kernel_launch(void* const* d_in, const int* in_sizes, int n_in,
                              void* d_out, int out_size) {
    const float* x     = (const float*)d_in[0];
    const float* dw_w  = (const float*)d_in[1];
    const float* dw_b  = (const float*)d_in[2];
    const float* pw_w  = (const float*)d_in[3];
    const float* pw_b  = (const float*)d_in[4];
    const float* off_w = (const float*)d_in[5];
    const float* off_b = (const float*)d_in[6];
    const float* dc_w  = (const float*)d_in[7];
    const float* dc_b  = (const float*)d_in[8];
    const float* ln_g  = (const float*)d_in[9];
    const float* ln_b  = (const float*)d_in[10];
    float* out = (float*)d_out;

    cudaFuncSetAttribute(dwpw_kernel, cudaFuncAttributeMaxDynamicSharedMemorySize,
                         DWPW_SMEM);
    cudaFuncSetAttribute(off_kernel, cudaFuncAttributeMaxDynamicSharedMemorySize,
                         9 * 18 * 128 * 4);
    cudaFuncSetAttribute(fused_kernel, cudaFuncAttributeMaxDynamicSharedMemorySize,
                         FUSED_SMEM);

    prep_kernel<<<576, 256>>>(dc_w, pw_w, off_w);
    dwpw_kernel<<<1152, 256, DWPW_SMEM>>>(x, dw_w, dw_b, pw_b);
    mr_kernel<<<2, 256>>>();
    off_kernel<<<1152, 256, 9 * 18 * 128 * 4>>>(off_b);
    fused_kernel<<<576, 256, FUSED_SMEM>>>(dc_b, ln_g, ln_b, out);
}

// round 14
// speedup vs baseline: 2.1809x; 1.0367x over previous
#include <cuda_runtime.h>
#include <cstdint>

// ---------------------------------------------------------------------------
// DASAttentionGate. B=4, C=O=128, H=W=96, fp32.
// [dw3x3+pw1x1+stats fused] -> mr -> offconv3x3 (TF32x3 MMA) ->
//   [fused: gather(norm on the fly) -> mma.sync TF32x3 -> LN -> sigmoid gate]
// ---------------------------------------------------------------------------

#define Cc   128
#define Hc   96
#define Wc   96
#define HW   9216
#define PIX  36864

__device__ float g_h2[PIX * Cc];          // pw out, NHWC (pre-norm)
__device__ float g_stats[1024];
__device__ float g_mr[1024];              // mean[512], rstd[512]
__device__ float g_off[PIX * 18];
__device__ float g_offwB[9 * 32 * 128];   // off weights per tap [n(pad32)][c]
__device__ float g_pwT[128 * 128];
__device__ float g_wB[9 * 16384];         // deform weights per tap: [n*128+c]

// -------------------- TF32 helpers ------------------------------------------
__device__ __forceinline__ uint32_t tf32r(float v) {
    uint32_t r;
    asm("cvt.rna.tf32.f32 %0, %1;" : "=r"(r) : "f"(v));
    return r;
}

#define MMA_TF32(D, A, B0, B1)                                              \
    asm volatile("mma.sync.aligned.m16n8k8.row.col.f32.tf32.tf32.f32 "      \
        "{%0,%1,%2,%3}, {%4,%5,%6,%7}, {%8,%9}, {%0,%1,%2,%3};"             \
        : "+f"((D)[0]), "+f"((D)[1]), "+f"((D)[2]), "+f"((D)[3])            \
        : "r"((A)[0]), "r"((A)[1]), "r"((A)[2]), "r"((A)[3]),               \
          "r"(B0), "r"(B1))

// -------------------- prep: weight images + zero stats ----------------------
__global__ void prep_kernel(const float* __restrict__ dc_w,
                            const float* __restrict__ pw_w,
                            const float* __restrict__ off_w) {
    int i = blockIdx.x * blockDim.x + threadIdx.x;
    if (i < 9 * 16384) {
        int tap = i >> 14;
        int r   = i & 16383;
        int n   = r >> 7, c = r & 127;
        g_wB[i] = dc_w[(n * 128 + c) * 9 + tap];
    }
    if (i < 128 * 128) {
        int c = i >> 7, o = i & 127;
        g_pwT[i] = pw_w[o * 128 + c];
    }
    if (i < 9 * 32 * 128) {
        int tap = i >> 12;
        int r   = i & 4095;
        int n   = r >> 7, c = r & 127;
        g_offwB[i] = (n < 18) ? off_w[(n * 128 + c) * 9 + tap] : 0.f;
    }
    if (i < 1024) g_stats[i] = 0.f;
}

// ---------------------------------------------------------------------------
// Fused depthwise 3x3 + pointwise 1x1 + InstanceNorm stats.
// ---------------------------------------------------------------------------
#define DWPW_SMEM ((13056 + 4096) * 4)

__global__ __launch_bounds__(256) void dwpw_kernel(
        const float* __restrict__ x,
        const float* __restrict__ dw_w,
        const float* __restrict__ dw_b,
        const float* __restrict__ pw_b) {
    extern __shared__ float smd[];
    float* xt = smd;            // [c][r][34]
    float* sS = smd + 13056;    // [c][32]

    int t  = threadIdx.x;
    int p0 = blockIdx.x * 32;
    int b  = p0 / HW;
    int s0 = p0 - b * HW;
    int y  = s0 / Wc;
    int x0 = s0 - y * Wc;

    for (int f = t; f < 13056; f += 256) {
        int c   = f / 102;
        int rem = f - c * 102;
        int r   = rem / 34;
        int col = rem - r * 34;
        int yy = y + r - 1, xx = x0 + col - 1;
        float v = 0.f;
        if ((unsigned)yy < Hc && (unsigned)xx < Wc)
            v = x[(size_t)(b * 128 + c) * HW + yy * Wc + xx];
        xt[f] = v;
    }
    __syncthreads();

    {
        int c   = t >> 1;
        int pxb = (t & 1) * 16;
        float wv[9];
#pragma unroll
        for (int j = 0; j < 9; j++) wv[j] = dw_w[c * 9 + j];
        float bias = dw_b[c];
        float accd[16];
#pragma unroll
        for (int p = 0; p < 16; p++) accd[p] = bias;
#pragma unroll
        for (int r = 0; r < 3; r++)
#pragma unroll
            for (int cc = 0; cc < 3; cc++) {
                float wgt = wv[r * 3 + cc];
                const float* src = &xt[c * 102 + r * 34 + pxb + cc];
#pragma unroll
                for (int p = 0; p < 16; p++) accd[p] += wgt * src[p];
            }
#pragma unroll
        for (int p = 0; p < 16; p++) sS[c * 32 + pxb + p] = accd[p];
    }
    __syncthreads();

    int px0 = (t & 7) * 4;
    int o0  = (t >> 3) * 4;
    float acc[4][4];
#pragma unroll
    for (int p = 0; p < 4; p++)
#pragma unroll
        for (int q = 0; q < 4; q++) acc[p][q] = 0.f;
#pragma unroll 4
    for (int c = 0; c < 128; c++) {
        float4 sv = *(const float4*)&sS[c * 32 + px0];
        float4 wv = __ldg((const float4*)&g_pwT[c * 128 + o0]);
        float sm[4] = {sv.x, sv.y, sv.z, sv.w};
        float wm[4] = {wv.x, wv.y, wv.z, wv.w};
#pragma unroll
        for (int p = 0; p < 4; p++)
#pragma unroll
            for (int q = 0; q < 4; q++) acc[p][q] += sm[p] * wm[q];
    }
    float sp[4], sq[4];
#pragma unroll
    for (int q = 0; q < 4; q++) { sp[q] = 0.f; sq[q] = 0.f; }
#pragma unroll
    for (int p = 0; p < 4; p++) {
        float4 o;
        o.x = acc[p][0] + pw_b[o0];
        o.y = acc[p][1] + pw_b[o0 + 1];
        o.z = acc[p][2] + pw_b[o0 + 2];
        o.w = acc[p][3] + pw_b[o0 + 3];
        sp[0] += o.x; sq[0] += o.x * o.x;
        sp[1] += o.y; sq[1] += o.y * o.y;
        sp[2] += o.z; sq[2] += o.z * o.z;
        sp[3] += o.w; sq[3] += o.w * o.w;
        *(float4*)&g_h2[(size_t)(p0 + px0 + p) * 128 + o0] = o;
    }
#pragma unroll
    for (int q = 0; q < 4; q++) {
#pragma unroll
        for (int o = 1; o < 8; o <<= 1) {
            sp[q] += __shfl_xor_sync(0xffffffffu, sp[q], o);
            sq[q] += __shfl_xor_sync(0xffffffffu, sq[q], o);
        }
    }
    if ((t & 7) == 0) {
#pragma unroll
        for (int q = 0; q < 4; q++) {
            atomicAdd(&g_stats[b * 128 + o0 + q], sp[q]);
            atomicAdd(&g_stats[512 + b * 128 + o0 + q], sq[q]);
        }
    }
}

// -------------------- instance norm finalize ---------------------------------
__global__ void mr_kernel() {
    int i = blockIdx.x * blockDim.x + threadIdx.x;
    if (i >= 512) return;
    float m = g_stats[i] * (1.f / HW);
    float v = g_stats[512 + i] * (1.f / HW) - m * m;
    g_mr[i] = m;
    g_mr[512 + i] = rsqrtf(v + 1e-5f);
}

// ---------------------------------------------------------------------------
// Offset conv 3x3 via TF32x3 MMA: [128px x 1152] * [1152 x 18(pad32)].
// Block: 128 px, 256 threads = 8 warps (4M x 2N), warp M32 x N16.
// smem: As[128][132] + Bs[32][132] = 84.5KB -> 2 CTAs/SM.
// ---------------------------------------------------------------------------
#define PITCH 132
#define OFF_SMEM ((128 * PITCH + 32 * PITCH) * 4)

__global__ __launch_bounds__(256, 2) void off_mma_kernel(
        const float* __restrict__ off_b) {
    extern __shared__ float smo[];
    float* As = smo;                    // [px][PITCH], 128 rows
    float* Bs = smo + 128 * PITCH;      // [n][PITCH], 32 rows

    int t = threadIdx.x;
    int w = t >> 5, l = t & 31;
    int m0 = blockIdx.x * 128;
    int b  = m0 / HW;
    int s0 = m0 - b * HW;
    const float* img = g_h2 + (size_t)b * HW * 128;

    int mbase = (w & 3) * 32;
    int nbase = (w >> 2) * 16;
    int qr = l >> 2;
    int qc = l & 3;
    int c0 = 4 * l;

    float4 m4 = *(const float4*)&g_mr[b * 128 + c0];
    float4 r4 = *(const float4*)&g_mr[512 + b * 128 + c0];

    float d[2][2][4];
#pragma unroll
    for (int i = 0; i < 2; i++)
#pragma unroll
        for (int j = 0; j < 2; j++)
#pragma unroll
            for (int q = 0; q < 4; q++) d[i][j][q] = 0.f;

    for (int tap = 0; tap < 9; tap++) {
        __syncthreads();

        // ---- regular tap gather (norm on the fly, zero OOB) ----
        {
            int dy = tap / 3 - 1, dx = tap % 3 - 1;
#pragma unroll 2
            for (int ii = 0; ii < 16; ii++) {
                int px = w * 16 + ii;
                int s  = s0 + px;
                int y  = s / Wc, xw = s - y * Wc;
                int yy = y + dy, xx = xw + dx;
                float4 v = make_float4(0.f, 0.f, 0.f, 0.f);
                if ((unsigned)yy < Hc && (unsigned)xx < Wc) {
                    float4 raw = *(const float4*)&img[(size_t)(yy * Wc + xx) * 128 + c0];
                    v.x = (raw.x - m4.x) * r4.x;
                    v.y = (raw.y - m4.y) * r4.y;
                    v.z = (raw.z - m4.z) * r4.z;
                    v.w = (raw.w - m4.w) * r4.w;
                }
                *(float4*)&As[px * PITCH + c0] = v;
            }
        }

        // ---- copy B tap [32 x 128] ----
        {
            const float4* src = (const float4*)(g_offwB + (tap << 12));
#pragma unroll
            for (int j = 0; j < 4; j++) {
                int f4 = t + j * 256;          // 0..1023
                int n = f4 >> 5, c4 = (f4 & 31) << 2;
                *(float4*)&Bs[n * PITCH + c4] = src[f4];
            }
        }
        __syncthreads();

        // ---- 16 K8-steps of TF32x3 mma ----
#pragma unroll 4
        for (int s = 0; s < 16; s++) {
            int k0 = s * 8;
            uint32_t ah[2][4], al[2][4];
#pragma unroll
            for (int mi = 0; mi < 2; mi++) {
                int r0 = (mbase + mi * 16 + qr) * PITCH + k0 + qc;
                int r1 = r0 + 8 * PITCH;
                float f0 = As[r0], f1 = As[r1], f2 = As[r0 + 4], f3 = As[r1 + 4];
                ah[mi][0] = tf32r(f0);
                ah[mi][1] = tf32r(f1);
                ah[mi][2] = tf32r(f2);
                ah[mi][3] = tf32r(f3);
                al[mi][0] = __float_as_uint(f0 - __uint_as_float(ah[mi][0]));
                al[mi][1] = __float_as_uint(f1 - __uint_as_float(ah[mi][1]));
                al[mi][2] = __float_as_uint(f2 - __uint_as_float(ah[mi][2]));
                al[mi][3] = __float_as_uint(f3 - __uint_as_float(ah[mi][3]));
            }
            uint32_t bh[2][2], bl[2][2];
#pragma unroll
            for (int ni = 0; ni < 2; ni++) {
                int nb = (nbase + ni * 8 + qr) * PITCH + k0 + qc;
                float f0 = Bs[nb], f1 = Bs[nb + 4];
                bh[ni][0] = tf32r(f0);
                bh[ni][1] = tf32r(f1);
                bl[ni][0] = __float_as_uint(f0 - __uint_as_float(bh[ni][0]));
                bl[ni][1] = __float_as_uint(f1 - __uint_as_float(bh[ni][1]));
            }
#pragma unroll
            for (int mi = 0; mi < 2; mi++)
#pragma unroll
                for (int ni = 0; ni < 2; ni++) {
                    MMA_TF32(d[mi][ni], ah[mi], bh[ni][0], bh[ni][1]);
                    MMA_TF32(d[mi][ni], ah[mi], bl[ni][0], bl[ni][1]);
                    MMA_TF32(d[mi][ni], al[mi], bh[ni][0], bh[ni][1]);
                }
        }
    }

    // ---- epilogue: bias + write n<18 directly to g_off ----
#pragma unroll
    for (int mi = 0; mi < 2; mi++) {
        int row = mbase + mi * 16 + qr;
#pragma unroll
        for (int ni = 0; ni < 2; ni++) {
            int col = nbase + ni * 8 + 2 * qc;
            if (col < 18) {
                float b0 = off_b[col], b1 = off_b[col + 1];
                float2 lo, hi;
                lo.x = d[mi][ni][0] + b0; lo.y = d[mi][ni][1] + b1;
                hi.x = d[mi][ni][2] + b0; hi.y = d[mi][ni][3] + b1;
                *(float2*)&g_off[(size_t)(m0 + row) * 18 + col]     = lo;
                *(float2*)&g_off[(size_t)(m0 + row + 8) * 18 + col] = hi;
            }
        }
    }
}

// ---------------------------------------------------------------------------
// Fused deform conv via mma.sync m16n8k8 TF32x3, norm folded into gather.
// Block: 64 px (M) x 128 out (N), 256 threads = 8 warps (2M x 4N), 2 CTAs/SM.
// ---------------------------------------------------------------------------
#define FUSED_SMEM ((64 * PITCH + 128 * PITCH) * 4)

__global__ __launch_bounds__(256, 2) void fused_kernel(
        const float* __restrict__ dc_b,
        const float* __restrict__ ln_g,
        const float* __restrict__ ln_b,
        float* __restrict__ out) {
    extern __shared__ float smf[];
    float* As = smf;                    // [px][PITCH], 64 rows
    float* Bs = smf + 64 * PITCH;       // [n][PITCH], 128 rows

    int t = threadIdx.x;
    int w = t >> 5, l = t & 31;
    int m0 = blockIdx.x * 64;
    int b  = m0 / HW;
    int s0 = m0 - b * HW;
    const float* img = g_h2 + (size_t)b * HW * 128;

    int mbase = (w & 1) * 32;
    int nbase = (w >> 1) * 32;
    int qr = l >> 2;
    int qc = l & 3;
    int c0 = 4 * l;

    float4 m4 = *(const float4*)&g_mr[b * 128 + c0];
    float4 r4 = *(const float4*)&g_mr[512 + b * 128 + c0];

    float d[2][4][4];
#pragma unroll
    for (int i = 0; i < 2; i++)
#pragma unroll
        for (int j = 0; j < 4; j++)
#pragma unroll
            for (int q = 0; q < 4; q++) d[i][j][q] = 0.f;

    for (int tap = 0; tap < 9; tap++) {
        __syncthreads();

        // ---- gather tap into As (normalized on the fly via wsum trick) ----
        {
            int dy = tap / 3 - 1, dx = tap % 3 - 1;
#pragma unroll 2
            for (int ii = 0; ii < 8; ii++) {
                int px = w * 8 + ii;
                int s  = s0 + px;
                int y  = s / Wc, xw = s - y * Wc;
                float2 o = *(const float2*)&g_off[(size_t)(m0 + px) * 18 + 2 * tap];
                float ys = (float)(y + dy) + o.x;
                float xs = (float)(xw + dx) + o.y;
                float y0f = floorf(ys), x0f = floorf(xs);
                float wy = ys - y0f, wx = xs - x0f;
                int y0i = (int)y0f, x0i = (int)x0f;
                int y1i = y0i + 1, x1i = x0i + 1;
                float w00 = (1.f - wy) * (1.f - wx);
                float w01 = (1.f - wy) * wx;
                float w10 = wy * (1.f - wx);
                float w11 = wy * wx;
                bool vy0 = (unsigned)y0i < (unsigned)Hc;
                bool vy1 = (unsigned)y1i < (unsigned)Hc;
                bool vx0 = (unsigned)x0i < (unsigned)Wc;
                bool vx1 = (unsigned)x1i < (unsigned)Wc;
                if (!(vy0 && vx0)) w00 = 0.f;
                if (!(vy0 && vx1)) w01 = 0.f;
                if (!(vy1 && vx0)) w10 = 0.f;
                if (!(vy1 && vx1)) w11 = 0.f;
                float wsum = w00 + w01 + w10 + w11;
                int yc0 = min(Hc - 1, max(0, y0i));
                int yc1 = min(Hc - 1, max(0, y1i));
                int xc0 = min(Wc - 1, max(0, x0i));
                int xc1 = min(Wc - 1, max(0, x1i));
                float4 v00 = *(const float4*)&img[(size_t)(yc0 * Wc + xc0) * 128 + c0];
                float4 v01 = *(const float4*)&img[(size_t)(yc0 * Wc + xc1) * 128 + c0];
                float4 v10 = *(const float4*)&img[(size_t)(yc1 * Wc + xc0) * 128 + c0];
                float4 v11 = *(const float4*)&img[(size_t)(yc1 * Wc + xc1) * 128 + c0];
                float4 r;
                r.x = w00 * v00.x + w01 * v01.x + w10 * v10.x + w11 * v11.x;
                r.y = w00 * v00.y + w01 * v01.y + w10 * v10.y + w11 * v11.y;
                r.z = w00 * v00.z + w01 * v01.z + w10 * v10.z + w11 * v11.z;
                r.w = w00 * v00.w + w01 * v01.w + w10 * v10.w + w11 * v11.w;
                r.x = (r.x - m4.x * wsum) * r4.x;
                r.y = (r.y - m4.y * wsum) * r4.y;
                r.z = (r.z - m4.z * wsum) * r4.z;
                r.w = (r.w - m4.w * wsum) * r4.w;
                *(float4*)&As[px * PITCH + c0] = r;
            }
        }

        // ---- copy B tap into Bs[n][PITCH] ----
        {
            const float4* src = (const float4*)(g_wB + (tap << 14));
#pragma unroll
            for (int j = 0; j < 16; j++) {
                int f4 = t + j * 256;
                int n = f4 >> 5, c4 = (f4 & 31) << 2;
                *(float4*)&Bs[n * PITCH + c4] = src[f4];
            }
        }
        __syncthreads();

        // ---- 16 K8-steps of TF32x3 mma ----
#pragma unroll 4
        for (int s = 0; s < 16; s++) {
            int k0 = s * 8;
            uint32_t ah[2][4], al[2][4];
#pragma unroll
            for (int mi = 0; mi < 2; mi++) {
                int r0 = (mbase + mi * 16 + qr) * PITCH + k0 + qc;
                int r1 = r0 + 8 * PITCH;
                float f0 = As[r0], f1 = As[r1], f2 = As[r0 + 4], f3 = As[r1 + 4];
                ah[mi][0] = tf32r(f0);
                ah[mi][1] = tf32r(f1);
                ah[mi][2] = tf32r(f2);
                ah[mi][3] = tf32r(f3);
                al[mi][0] = __float_as_uint(f0 - __uint_as_float(ah[mi][0]));
                al[mi][1] = __float_as_uint(f1 - __uint_as_float(ah[mi][1]));
                al[mi][2] = __float_as_uint(f2 - __uint_as_float(ah[mi][2]));
                al[mi][3] = __float_as_uint(f3 - __uint_as_float(ah[mi][3]));
            }
            uint32_t bh[4][2], bl[4][2];
#pragma unroll
            for (int ni = 0; ni < 4; ni++) {
                int nb = (nbase + ni * 8 + qr) * PITCH + k0 + qc;
                float f0 = Bs[nb], f1 = Bs[nb + 4];
                bh[ni][0] = tf32r(f0);
                bh[ni][1] = tf32r(f1);
                bl[ni][0] = __float_as_uint(f0 - __uint_as_float(bh[ni][0]));
                bl[ni][1] = __float_as_uint(f1 - __uint_as_float(bh[ni][1]));
            }
#pragma unroll
            for (int mi = 0; mi < 2; mi++)
#pragma unroll
                for (int ni = 0; ni < 4; ni++) {
                    MMA_TF32(d[mi][ni], ah[mi], bh[ni][0], bh[ni][1]);
                    MMA_TF32(d[mi][ni], ah[mi], bl[ni][0], bl[ni][1]);
                    MMA_TF32(d[mi][ni], al[mi], bh[ni][0], bh[ni][1]);
                }
        }
    }

    // ---- epilogue: bias + stage into sdc[px][PITCH] ----
    __syncthreads();
    float* sdc = smf;
#pragma unroll
    for (int mi = 0; mi < 2; mi++) {
        int row0 = mbase + mi * 16 + qr;
#pragma unroll
        for (int ni = 0; ni < 4; ni++) {
            int col = nbase + ni * 8 + 2 * qc;
            float b0 = dc_b[col], b1 = dc_b[col + 1];
            float2 lo, hi;
            lo.x = d[mi][ni][0] + b0; lo.y = d[mi][ni][1] + b1;
            hi.x = d[mi][ni][2] + b0; hi.y = d[mi][ni][3] + b1;
            *(float2*)&sdc[row0 * PITCH + col]       = lo;
            *(float2*)&sdc[(row0 + 8) * PITCH + col] = hi;
        }
    }
    __syncthreads();

    // ---- LayerNorm(C) + sigmoid gate (gate reads g_h2 + on-the-fly norm) ----
    {
        float4 gv = *(const float4*)&ln_g[c0];
        float4 bv = *(const float4*)&ln_b[c0];
#pragma unroll 1
        for (int ii = 0; ii < 8; ii++) {
            int px = w * 8 + ii;
            int pg = m0 + px;
            float4 dd = *(const float4*)&sdc[px * PITCH + c0];
            float s  = dd.x + dd.y + dd.z + dd.w;
            float s2 = dd.x * dd.x + dd.y * dd.y + dd.z * dd.z + dd.w * dd.w;
#pragma unroll
            for (int o = 16; o; o >>= 1) {
                s  += __shfl_xor_sync(0xffffffffu, s,  o);
                s2 += __shfl_xor_sync(0xffffffffu, s2, o);
            }
            float mean = s * (1.f / 128.f);
            float var  = s2 * (1.f / 128.f) - mean * mean;
            float rstd = rsqrtf(var + 1e-5f);
            float4 raw = *(const float4*)&g_h2[(size_t)pg * 128 + c0];
            float4 ds;
            ds.x = (raw.x - m4.x) * r4.x;
            ds.y = (raw.y - m4.y) * r4.y;
            ds.z = (raw.z - m4.z) * r4.z;
            ds.w = (raw.w - m4.w) * r4.w;
            float a;
            float4 r;
            a = (dd.x - mean) * rstd * gv.x + bv.x; r.x = ds.x / (1.f + expf(-a));
            a = (dd.y - mean) * rstd * gv.y + bv.y; r.y = ds.y / (1.f + expf(-a));
            a = (dd.z - mean) * rstd * gv.z + bv.z; r.z = ds.z / (1.f + expf(-a));
            a = (dd.w - mean) * rstd * gv.w + bv.w; r.w = ds.w / (1.f + expf(-a));
            *(float4*)&sdc[px * PITCH + c0] = r;
        }
    }
    __syncthreads();

    // ---- transpose-out: sdc[px][c] -> NCHW, coalesced ----
    {
        float* obase = out + (size_t)b * 128 * HW + s0;
#pragma unroll 1
        for (int j = 0; j < 32; j++) {
            int flat = t + j * 256;
            int c = flat >> 6, px = flat & 63;
            obase[(size_t)c * HW + px] = sdc[px * PITCH + c];
        }
    }
}

// ---------------------------------------------------------------------------
extern "C" void kernel_launch(void* const* d_in, const int* in_sizes, int n_in,
                              void* d_out, int out_size) {
    const float* x     = (const float*)d_in[0];
    const float* dw_w  = (const float*)d_in[1];
    const float* dw_b  = (const float*)d_in[2];
    const float* pw_w  = (const float*)d_in[3];
    const float* pw_b  = (const float*)d_in[4];
    const float* off_w = (const float*)d_in[5];
    const float* off_b = (const float*)d_in[6];
    const float* dc_w  = (const float*)d_in[7];
    const float* dc_b  = (const float*)d_in[8];
    const float* ln_g  = (const float*)d_in[9];
    const float* ln_b  = (const float*)d_in[10];
    float* out = (float*)d_out;

    cudaFuncSetAttribute(dwpw_kernel, cudaFuncAttributeMaxDynamicSharedMemorySize,
                         DWPW_SMEM);
    cudaFuncSetAttribute(off_mma_kernel, cudaFuncAttributeMaxDynamicSharedMemorySize,
                         OFF_SMEM);
    cudaFuncSetAttribute(fused_kernel, cudaFuncAttributeMaxDynamicSharedMemorySize,
                         FUSED_SMEM);

    prep_kernel<<<576, 256>>>(dc_w, pw_w, off_w);
    dwpw_kernel<<<1152, 256, DWPW_SMEM>>>(x, dw_w, dw_b, pw_b);
    mr_kernel<<<2, 256>>>();
    off_mma_kernel<<<288, 256, OFF_SMEM>>>(off_b);
    fused_kernel<<<576, 256, FUSED_SMEM>>>(dc_b, ln_g, ln_b, out);
}

// round 15
// speedup vs baseline: 2.3923x; 1.0969x over previous
#include <cuda_runtime.h>
#include <cstdint>

// ---------------------------------------------------------------------------
// DASAttentionGate. B=4, C=O=128, H=W=96, fp32.
// [dw3x3 + pw1x1(TF32x3 MMA) + stats] -> mr -> offconv3x3 (TF32 MMA, 1-pass)
//   -> [fused: gather(norm on the fly) -> mma.sync TF32x3 -> LN -> gate]
// ---------------------------------------------------------------------------

#define Cc   128
#define Hc   96
#define Wc   96
#define HW   9216
#define PIX  36864
#define PITCH 132

__device__ float g_h2[PIX * Cc];          // pw out, NHWC (pre-norm)
__device__ float g_stats[1024];
__device__ float g_mr[1024];              // mean[512], rstd[512]
__device__ float g_off[PIX * 18];
__device__ float g_offwB[9 * 32 * 128];   // off weights per tap [n(pad32)][c]
__device__ float g_wB[9 * 16384];         // deform weights per tap: [n*128+c]

// -------------------- TF32 helpers ------------------------------------------
__device__ __forceinline__ uint32_t tf32r(float v) {
    uint32_t r;
    asm("cvt.rna.tf32.f32 %0, %1;" : "=r"(r) : "f"(v));
    return r;
}

#define MMA_TF32(D, A, B0, B1)                                              \
    asm volatile("mma.sync.aligned.m16n8k8.row.col.f32.tf32.tf32.f32 "      \
        "{%0,%1,%2,%3}, {%4,%5,%6,%7}, {%8,%9}, {%0,%1,%2,%3};"             \
        : "+f"((D)[0]), "+f"((D)[1]), "+f"((D)[2]), "+f"((D)[3])            \
        : "r"((A)[0]), "r"((A)[1]), "r"((A)[2]), "r"((A)[3]),               \
          "r"(B0), "r"(B1))

// -------------------- prep: weight images + zero stats ----------------------
__global__ void prep_kernel(const float* __restrict__ dc_w,
                            const float* __restrict__ off_w) {
    int i = blockIdx.x * blockDim.x + threadIdx.x;
    if (i < 9 * 16384) {
        int tap = i >> 14;
        int r   = i & 16383;
        int n   = r >> 7, c = r & 127;
        g_wB[i] = dc_w[(n * 128 + c) * 9 + tap];
    }
    if (i < 9 * 32 * 128) {
        int tap = i >> 12;
        int r   = i & 4095;
        int n   = r >> 7, c = r & 127;
        g_offwB[i] = (n < 18) ? off_w[(n * 128 + c) * 9 + tap] : 0.f;
    }
    if (i < 1024) g_stats[i] = 0.f;
}

// ---------------------------------------------------------------------------
// Fused depthwise 3x3 + pointwise 1x1 (TF32x3 MMA) + InstanceNorm stats.
// Block = 32 px of one row, 256 threads = 8 warps (2M x 4N), warp M16 x N32.
// smem: As[32][132] (16.9KB) + Bs[128][132] (67.6KB); x-halo aliases Bs.
// ---------------------------------------------------------------------------
#define DWPW_SMEM ((32 * PITCH + 128 * PITCH) * 4)

__global__ __launch_bounds__(256, 2) void dwpw_kernel(
        const float* __restrict__ x,
        const float* __restrict__ dw_w,
        const float* __restrict__ dw_b,
        const float* __restrict__ pw_w,
        const float* __restrict__ pw_b) {
    extern __shared__ float smd[];
    float* As = smd;                    // [px][PITCH], 32 rows
    float* Bs = smd + 32 * PITCH;       // [o][PITCH], 128 rows
    float* xt = Bs;                     // halo aliases Bs: [c][r][34] = 13056

    int t  = threadIdx.x;
    int w  = t >> 5, l = t & 31;
    int p0 = blockIdx.x * 32;
    int b  = p0 / HW;
    int s0 = p0 - b * HW;
    int y  = s0 / Wc;
    int x0 = s0 - y * Wc;

    // ---- halo load ----
    for (int f = t; f < 13056; f += 256) {
        int c   = f / 102;
        int rem = f - c * 102;
        int r   = rem / 34;
        int col = rem - r * 34;
        int yy = y + r - 1, xx = x0 + col - 1;
        float v = 0.f;
        if ((unsigned)yy < Hc && (unsigned)xx < Wc)
            v = x[(size_t)(b * 128 + c) * HW + yy * Wc + xx];
        xt[f] = v;
    }
    __syncthreads();

    // ---- depthwise into As[px][c] ----
    {
        int c   = t >> 1;
        int pxb = (t & 1) * 16;
        float wv[9];
#pragma unroll
        for (int j = 0; j < 9; j++) wv[j] = dw_w[c * 9 + j];
        float bias = dw_b[c];
        float accd[16];
#pragma unroll
        for (int p = 0; p < 16; p++) accd[p] = bias;
#pragma unroll
        for (int r = 0; r < 3; r++)
#pragma unroll
            for (int cc = 0; cc < 3; cc++) {
                float wgt = wv[r * 3 + cc];
                const float* src = &xt[c * 102 + r * 34 + pxb + cc];
#pragma unroll
                for (int p = 0; p < 16; p++) accd[p] += wgt * src[p];
            }
#pragma unroll
        for (int p = 0; p < 16; p++) As[(pxb + p) * PITCH + c] = accd[p];
    }
    __syncthreads();

    // ---- load pw weights into Bs[o][c] (overwrites halo) ----
#pragma unroll
    for (int j = 0; j < 16; j++) {
        int f4 = t + j * 256;              // 0..4095
        int n = f4 >> 5, c4 = (f4 & 31) << 2;
        *(float4*)&Bs[n * PITCH + c4] = *(const float4*)&pw_w[n * 128 + c4];
    }
    __syncthreads();

    // ---- pw GEMM: [32 x 128] * [128 x 128], TF32x3 ----
    int mbase = (w & 1) * 16;
    int nbase = (w >> 1) * 32;
    int qr = l >> 2;
    int qc = l & 3;

    float d[4][4];
#pragma unroll
    for (int j = 0; j < 4; j++)
#pragma unroll
        for (int q = 0; q < 4; q++) d[j][q] = 0.f;

#pragma unroll 4
    for (int s = 0; s < 16; s++) {
        int k0 = s * 8;
        uint32_t ah[4], al[4];
        {
            int r0 = (mbase + qr) * PITCH + k0 + qc;
            int r1 = r0 + 8 * PITCH;
            float f0 = As[r0], f1 = As[r1], f2 = As[r0 + 4], f3 = As[r1 + 4];
            ah[0] = tf32r(f0); ah[1] = tf32r(f1);
            ah[2] = tf32r(f2); ah[3] = tf32r(f3);
            al[0] = __float_as_uint(f0 - __uint_as_float(ah[0]));
            al[1] = __float_as_uint(f1 - __uint_as_float(ah[1]));
            al[2] = __float_as_uint(f2 - __uint_as_float(ah[2]));
            al[3] = __float_as_uint(f3 - __uint_as_float(ah[3]));
        }
        uint32_t bh[4][2], bl[4][2];
#pragma unroll
        for (int ni = 0; ni < 4; ni++) {
            int nb = (nbase + ni * 8 + qr) * PITCH + k0 + qc;
            float f0 = Bs[nb], f1 = Bs[nb + 4];
            bh[ni][0] = tf32r(f0);
            bh[ni][1] = tf32r(f1);
            bl[ni][0] = __float_as_uint(f0 - __uint_as_float(bh[ni][0]));
            bl[ni][1] = __float_as_uint(f1 - __uint_as_float(bh[ni][1]));
        }
#pragma unroll
        for (int ni = 0; ni < 4; ni++) {
            MMA_TF32(d[ni], ah, bh[ni][0], bh[ni][1]);
            MMA_TF32(d[ni], ah, bl[ni][0], bl[ni][1]);
            MMA_TF32(d[ni], al, bh[ni][0], bh[ni][1]);
        }
    }
    __syncthreads();

    // ---- bias + stage result back into As (sdc[32][PITCH]) ----
    float* sdc = As;
    {
        int row = mbase + qr;
#pragma unroll
        for (int ni = 0; ni < 4; ni++) {
            int col = nbase + ni * 8 + 2 * qc;
            float b0 = pw_b[col], b1 = pw_b[col + 1];
            float2 lo, hi;
            lo.x = d[ni][0] + b0; lo.y = d[ni][1] + b1;
            hi.x = d[ni][2] + b0; hi.y = d[ni][3] + b1;
            *(float2*)&sdc[row * PITCH + col]       = lo;
            *(float2*)&sdc[(row + 8) * PITCH + col] = hi;
        }
    }
    __syncthreads();

    // ---- stats + write g_h2 ----
    {
        int c   = t >> 1;
        int pxb = (t & 1) * 16;
        float sp = 0.f, sq = 0.f;
#pragma unroll
        for (int p = 0; p < 16; p++) {
            float v = sdc[(pxb + p) * PITCH + c];
            sp += v; sq += v * v;
        }
        sp += __shfl_xor_sync(0xffffffffu, sp, 1);
        sq += __shfl_xor_sync(0xffffffffu, sq, 1);
        if ((t & 1) == 0) {
            atomicAdd(&g_stats[b * 128 + c], sp);
            atomicAdd(&g_stats[512 + b * 128 + c], sq);
        }
    }
#pragma unroll
    for (int j = 0; j < 16; j++) {
        int flat = t + j * 256;            // 0..4095
        int px = flat >> 7, c = flat & 127;
        g_h2[(size_t)(p0 + px) * 128 + c] = sdc[px * PITCH + c];
    }
}

// -------------------- instance norm finalize ---------------------------------
__global__ void mr_kernel() {
    int i = blockIdx.x * blockDim.x + threadIdx.x;
    if (i >= 512) return;
    float m = g_stats[i] * (1.f / HW);
    float v = g_stats[512 + i] * (1.f / HW) - m * m;
    g_mr[i] = m;
    g_mr[512 + i] = rsqrtf(v + 1e-5f);
}

// ---------------------------------------------------------------------------
// Offset conv 3x3 via single-pass TF32 MMA: [128px x 1152] * [1152 x 18(pad)].
// Block: 128 px, 256 threads = 8 warps (4M x 2N), warp M32 x N16.
// ---------------------------------------------------------------------------
#define OFF_SMEM ((128 * PITCH + 32 * PITCH) * 4)

__global__ __launch_bounds__(256, 2) void off_mma_kernel(
        const float* __restrict__ off_b) {
    extern __shared__ float smo[];
    float* As = smo;                    // [px][PITCH], 128 rows
    float* Bs = smo + 128 * PITCH;      // [n][PITCH], 32 rows

    int t = threadIdx.x;
    int w = t >> 5, l = t & 31;
    int m0 = blockIdx.x * 128;
    int b  = m0 / HW;
    int s0 = m0 - b * HW;
    const float* img = g_h2 + (size_t)b * HW * 128;

    int mbase = (w & 3) * 32;
    int nbase = (w >> 2) * 16;
    int qr = l >> 2;
    int qc = l & 3;
    int c0 = 4 * l;

    float4 m4 = *(const float4*)&g_mr[b * 128 + c0];
    float4 r4 = *(const float4*)&g_mr[512 + b * 128 + c0];

    float d[2][2][4];
#pragma unroll
    for (int i = 0; i < 2; i++)
#pragma unroll
        for (int j = 0; j < 2; j++)
#pragma unroll
            for (int q = 0; q < 4; q++) d[i][j][q] = 0.f;

    for (int tap = 0; tap < 9; tap++) {
        __syncthreads();

        // ---- regular tap gather (norm on the fly, zero OOB) ----
        {
            int dy = tap / 3 - 1, dx = tap % 3 - 1;
#pragma unroll 2
            for (int ii = 0; ii < 16; ii++) {
                int px = w * 16 + ii;
                int s  = s0 + px;
                int y  = s / Wc, xw = s - y * Wc;
                int yy = y + dy, xx = xw + dx;
                float4 v = make_float4(0.f, 0.f, 0.f, 0.f);
                if ((unsigned)yy < Hc && (unsigned)xx < Wc) {
                    float4 raw = *(const float4*)&img[(size_t)(yy * Wc + xx) * 128 + c0];
                    v.x = (raw.x - m4.x) * r4.x;
                    v.y = (raw.y - m4.y) * r4.y;
                    v.z = (raw.z - m4.z) * r4.z;
                    v.w = (raw.w - m4.w) * r4.w;
                }
                *(float4*)&As[px * PITCH + c0] = v;
            }
        }

        // ---- copy B tap [32 x 128] ----
        {
            const float4* src = (const float4*)(g_offwB + (tap << 12));
#pragma unroll
            for (int j = 0; j < 4; j++) {
                int f4 = t + j * 256;
                int n = f4 >> 5, c4 = (f4 & 31) << 2;
                *(float4*)&Bs[n * PITCH + c4] = src[f4];
            }
        }
        __syncthreads();

        // ---- 16 K8-steps, single-pass TF32 ----
#pragma unroll 4
        for (int s = 0; s < 16; s++) {
            int k0 = s * 8;
            uint32_t ah[2][4];
#pragma unroll
            for (int mi = 0; mi < 2; mi++) {
                int r0 = (mbase + mi * 16 + qr) * PITCH + k0 + qc;
                int r1 = r0 + 8 * PITCH;
                ah[mi][0] = tf32r(As[r0]);
                ah[mi][1] = tf32r(As[r1]);
                ah[mi][2] = tf32r(As[r0 + 4]);
                ah[mi][3] = tf32r(As[r1 + 4]);
            }
            uint32_t bh[2][2];
#pragma unroll
            for (int ni = 0; ni < 2; ni++) {
                if (nbase + ni * 8 < 24) {
                    int nb = (nbase + ni * 8 + qr) * PITCH + k0 + qc;
                    bh[ni][0] = tf32r(Bs[nb]);
                    bh[ni][1] = tf32r(Bs[nb + 4]);
                }
            }
#pragma unroll
            for (int mi = 0; mi < 2; mi++)
#pragma unroll
                for (int ni = 0; ni < 2; ni++)
                    if (nbase + ni * 8 < 24)
                        MMA_TF32(d[mi][ni], ah[mi], bh[ni][0], bh[ni][1]);
        }
    }

    // ---- epilogue: bias + write n<18 directly to g_off ----
#pragma unroll
    for (int mi = 0; mi < 2; mi++) {
        int row = mbase + mi * 16 + qr;
#pragma unroll
        for (int ni = 0; ni < 2; ni++) {
            int col = nbase + ni * 8 + 2 * qc;
            if (col < 18) {
                float b0 = off_b[col], b1 = off_b[col + 1];
                float2 lo, hi;
                lo.x = d[mi][ni][0] + b0; lo.y = d[mi][ni][1] + b1;
                hi.x = d[mi][ni][2] + b0; hi.y = d[mi][ni][3] + b1;
                *(float2*)&g_off[(size_t)(m0 + row) * 18 + col]     = lo;
                *(float2*)&g_off[(size_t)(m0 + row + 8) * 18 + col] = hi;
            }
        }
    }
}

// ---------------------------------------------------------------------------
// Fused deform conv via mma.sync m16n8k8 TF32x3, norm folded into gather.
// Block: 64 px (M) x 128 out (N), 256 threads = 8 warps (2M x 4N), 2 CTAs/SM.
// ---------------------------------------------------------------------------
#define FUSED_SMEM ((64 * PITCH + 128 * PITCH) * 4)

__global__ __launch_bounds__(256, 2) void fused_kernel(
        const float* __restrict__ dc_b,
        const float* __restrict__ ln_g,
        const float* __restrict__ ln_b,
        float* __restrict__ out) {
    extern __shared__ float smf[];
    float* As = smf;                    // [px][PITCH], 64 rows
    float* Bs = smf + 64 * PITCH;       // [n][PITCH], 128 rows

    int t = threadIdx.x;
    int w = t >> 5, l = t & 31;
    int m0 = blockIdx.x * 64;
    int b  = m0 / HW;
    int s0 = m0 - b * HW;
    const float* img = g_h2 + (size_t)b * HW * 128;

    int mbase = (w & 1) * 32;
    int nbase = (w >> 1) * 32;
    int qr = l >> 2;
    int qc = l & 3;
    int c0 = 4 * l;

    float4 m4 = *(const float4*)&g_mr[b * 128 + c0];
    float4 r4 = *(const float4*)&g_mr[512 + b * 128 + c0];

    float d[2][4][4];
#pragma unroll
    for (int i = 0; i < 2; i++)
#pragma unroll
        for (int j = 0; j < 4; j++)
#pragma unroll
            for (int q = 0; q < 4; q++) d[i][j][q] = 0.f;

    for (int tap = 0; tap < 9; tap++) {
        __syncthreads();

        // ---- gather tap into As (normalized on the fly via wsum trick) ----
        {
            int dy = tap / 3 - 1, dx = tap % 3 - 1;
#pragma unroll 2
            for (int ii = 0; ii < 8; ii++) {
                int px = w * 8 + ii;
                int s  = s0 + px;
                int y  = s / Wc, xw = s - y * Wc;
                float2 o = *(const float2*)&g_off[(size_t)(m0 + px) * 18 + 2 * tap];
                float ys = (float)(y + dy) + o.x;
                float xs = (float)(xw + dx) + o.y;
                float y0f = floorf(ys), x0f = floorf(xs);
                float wy = ys - y0f, wx = xs - x0f;
                int y0i = (int)y0f, x0i = (int)x0f;
                int y1i = y0i + 1, x1i = x0i + 1;
                float w00 = (1.f - wy) * (1.f - wx);
                float w01 = (1.f - wy) * wx;
                float w10 = wy * (1.f - wx);
                float w11 = wy * wx;
                bool vy0 = (unsigned)y0i < (unsigned)Hc;
                bool vy1 = (unsigned)y1i < (unsigned)Hc;
                bool vx0 = (unsigned)x0i < (unsigned)Wc;
                bool vx1 = (unsigned)x1i < (unsigned)Wc;
                if (!(vy0 && vx0)) w00 = 0.f;
                if (!(vy0 && vx1)) w01 = 0.f;
                if (!(vy1 && vx0)) w10 = 0.f;
                if (!(vy1 && vx1)) w11 = 0.f;
                float wsum = w00 + w01 + w10 + w11;
                int yc0 = min(Hc - 1, max(0, y0i));
                int yc1 = min(Hc - 1, max(0, y1i));
                int xc0 = min(Wc - 1, max(0, x0i));
                int xc1 = min(Wc - 1, max(0, x1i));
                float4 v00 = *(const float4*)&img[(size_t)(yc0 * Wc + xc0) * 128 + c0];
                float4 v01 = *(const float4*)&img[(size_t)(yc0 * Wc + xc1) * 128 + c0];
                float4 v10 = *(const float4*)&img[(size_t)(yc1 * Wc + xc0) * 128 + c0];
                float4 v11 = *(const float4*)&img[(size_t)(yc1 * Wc + xc1) * 128 + c0];
                float4 r;
                r.x = w00 * v00.x + w01 * v01.x + w10 * v10.x + w11 * v11.x;
                r.y = w00 * v00.y + w01 * v01.y + w10 * v10.y + w11 * v11.y;
                r.z = w00 * v00.z + w01 * v01.z + w10 * v10.z + w11 * v11.z;
                r.w = w00 * v00.w + w01 * v01.w + w10 * v10.w + w11 * v11.w;
                r.x = (r.x - m4.x * wsum) * r4.x;
                r.y = (r.y - m4.y * wsum) * r4.y;
                r.z = (r.z - m4.z * wsum) * r4.z;
                r.w = (r.w - m4.w * wsum) * r4.w;
                *(float4*)&As[px * PITCH + c0] = r;
            }
        }

        // ---- copy B tap into Bs[n][PITCH] ----
        {
            const float4* src = (const float4*)(g_wB + (tap << 14));
#pragma unroll
            for (int j = 0; j < 16; j++) {
                int f4 = t + j * 256;
                int n = f4 >> 5, c4 = (f4 & 31) << 2;
                *(float4*)&Bs[n * PITCH + c4] = src[f4];
            }
        }
        __syncthreads();

        // ---- 16 K8-steps of TF32x3 mma ----
#pragma unroll 4
        for (int s = 0; s < 16; s++) {
            int k0 = s * 8;
            uint32_t ah[2][4], al[2][4];
#pragma unroll
            for (int mi = 0; mi < 2; mi++) {
                int r0 = (mbase + mi * 16 + qr) * PITCH + k0 + qc;
                int r1 = r0 + 8 * PITCH;
                float f0 = As[r0], f1 = As[r1], f2 = As[r0 + 4], f3 = As[r1 + 4];
                ah[mi][0] = tf32r(f0);
                ah[mi][1] = tf32r(f1);
                ah[mi][2] = tf32r(f2);
                ah[mi][3] = tf32r(f3);
                al[mi][0] = __float_as_uint(f0 - __uint_as_float(ah[mi][0]));
                al[mi][1] = __float_as_uint(f1 - __uint_as_float(ah[mi][1]));
                al[mi][2] = __float_as_uint(f2 - __uint_as_float(ah[mi][2]));
                al[mi][3] = __float_as_uint(f3 - __uint_as_float(ah[mi][3]));
            }
            uint32_t bh[4][2], bl[4][2];
#pragma unroll
            for (int ni = 0; ni < 4; ni++) {
                int nb = (nbase + ni * 8 + qr) * PITCH + k0 + qc;
                float f0 = Bs[nb], f1 = Bs[nb + 4];
                bh[ni][0] = tf32r(f0);
                bh[ni][1] = tf32r(f1);
                bl[ni][0] = __float_as_uint(f0 - __uint_as_float(bh[ni][0]));
                bl[ni][1] = __float_as_uint(f1 - __uint_as_float(bh[ni][1]));
            }
#pragma unroll
            for (int mi = 0; mi < 2; mi++)
#pragma unroll
                for (int ni = 0; ni < 4; ni++) {
                    MMA_TF32(d[mi][ni], ah[mi], bh[ni][0], bh[ni][1]);
                    MMA_TF32(d[mi][ni], ah[mi], bl[ni][0], bl[ni][1]);
                    MMA_TF32(d[mi][ni], al[mi], bh[ni][0], bh[ni][1]);
                }
        }
    }

    // ---- epilogue: bias + stage into sdc[px][PITCH] ----
    __syncthreads();
    float* sdc = smf;
#pragma unroll
    for (int mi = 0; mi < 2; mi++) {
        int row0 = mbase + mi * 16 + qr;
#pragma unroll
        for (int ni = 0; ni < 4; ni++) {
            int col = nbase + ni * 8 + 2 * qc;
            float b0 = dc_b[col], b1 = dc_b[col + 1];
            float2 lo, hi;
            lo.x = d[mi][ni][0] + b0; lo.y = d[mi][ni][1] + b1;
            hi.x = d[mi][ni][2] + b0; hi.y = d[mi][ni][3] + b1;
            *(float2*)&sdc[row0 * PITCH + col]       = lo;
            *(float2*)&sdc[(row0 + 8) * PITCH + col] = hi;
        }
    }
    __syncthreads();

    // ---- LayerNorm(C) + sigmoid gate (gate reads g_h2 + on-the-fly norm) ----
    {
        float4 gv = *(const float4*)&ln_g[c0];
        float4 bv = *(const float4*)&ln_b[c0];
#pragma unroll 1
        for (int ii = 0; ii < 8; ii++) {
            int px = w * 8 + ii;
            int pg = m0 + px;
            float4 dd = *(const float4*)&sdc[px * PITCH + c0];
            float s  = dd.x + dd.y + dd.z + dd.w;
            float s2 = dd.x * dd.x + dd.y * dd.y + dd.z * dd.z + dd.w * dd.w;
#pragma unroll
            for (int o = 16; o; o >>= 1) {
                s  += __shfl_xor_sync(0xffffffffu, s,  o);
                s2 += __shfl_xor_sync(0xffffffffu, s2, o);
            }
            float mean = s * (1.f / 128.f);
            float var  = s2 * (1.f / 128.f) - mean * mean;
            float rstd = rsqrtf(var + 1e-5f);
            float4 raw = *(const float4*)&g_h2[(size_t)pg * 128 + c0];
            float4 ds;
            ds.x = (raw.x - m4.x) * r4.x;
            ds.y = (raw.y - m4.y) * r4.y;
            ds.z = (raw.z - m4.z) * r4.z;
            ds.w = (raw.w - m4.w) * r4.w;
            float a;
            float4 r;
            a = (dd.x - mean) * rstd * gv.x + bv.x; r.x = ds.x / (1.f + expf(-a));
            a = (dd.y - mean) * rstd * gv.y + bv.y; r.y = ds.y / (1.f + expf(-a));
            a = (dd.z - mean) * rstd * gv.z + bv.z; r.z = ds.z / (1.f + expf(-a));
            a = (dd.w - mean) * rstd * gv.w + bv.w; r.w = ds.w / (1.f + expf(-a));
            *(float4*)&sdc[px * PITCH + c0] = r;
        }
    }
    __syncthreads();

    // ---- transpose-out: sdc[px][c] -> NCHW, coalesced ----
    {
        float* obase = out + (size_t)b * 128 * HW + s0;
#pragma unroll 1
        for (int j = 0; j < 32; j++) {
            int flat = t + j * 256;
            int c = flat >> 6, px = flat & 63;
            obase[(size_t)c * HW + px] = sdc[px * PITCH + c];
        }
    }
}

// ---------------------------------------------------------------------------
extern "C" void kernel_launch(void* const* d_in, const int* in_sizes, int n_in,
                              void* d_out, int out_size) {
    const float* x     = (const float*)d_in[0];
    const float* dw_w  = (const float*)d_in[1];
    const float* dw_b  = (const float*)d_in[2];
    const float* pw_w  = (const float*)d_in[3];
    const float* pw_b  = (const float*)d_in[4];
    const float* off_w = (const float*)d_in[5];
    const float* off_b = (const float*)d_in[6];
    const float* dc_w  = (const float*)d_in[7];
    const float* dc_b  = (const float*)d_in[8];
    const float* ln_g  = (const float*)d_in[9];
    const float* ln_b  = (const float*)d_in[10];
    float* out = (float*)d_out;

    cudaFuncSetAttribute(dwpw_kernel, cudaFuncAttributeMaxDynamicSharedMemorySize,
                         DWPW_SMEM);
    cudaFuncSetAttribute(off_mma_kernel, cudaFuncAttributeMaxDynamicSharedMemorySize,
                         OFF_SMEM);
    cudaFuncSetAttribute(fused_kernel, cudaFuncAttributeMaxDynamicSharedMemorySize,
                         FUSED_SMEM);

    prep_kernel<<<576, 256>>>(dc_w, off_w);
    dwpw_kernel<<<1152, 256, DWPW_SMEM>>>(x, dw_w, dw_b, pw_w, pw_b);
    mr_kernel<<<2, 256>>>();
    off_mma_kernel<<<288, 256, OFF_SMEM>>>(off_b);
    fused_kernel<<<576, 256, FUSED_SMEM>>>(dc_b, ln_g, ln_b, out);
}